// round 12
// baseline (speedup 1.0000x reference)
#include <cuda_runtime.h>
#include <cuda_bf16.h>
#include <cuda_fp16.h>
#include <cstdint>

#define N_NODES 100000
#define N_EDGES 1600000
#define FEAT 128
#define NCAT 512
#define M_TILES ((N_NODES + 127) / 128)
#define PAD_K 136   // bf16 elements per SMEM row (272B: 16B-aligned, conflict-free frags)

// ---------------- scratch (static __device__, no allocation) ----------------
__device__ __align__(16) float g_qsk[(size_t)N_NODES * 256];   // [node][q(128)|sk(128)] fp32, streamed
__device__ __align__(16) __half g_kvh[(size_t)N_NODES * 256];  // [node][32 x (k4|v4)] fp16, gather set (51MB)
__device__ __align__(16) float g_h1[N_NODES * FEAT];
__device__ __align__(16) float g_h2[N_NODES * FEAT];
__device__ __align__(16) __nv_bfloat16 g_wbh[NCAT * FEAT];  // B[n][k] = W[k][n], hi
__device__ __align__(16) __nv_bfloat16 g_wbl[NCAT * FEAT];  // lo
__device__ __align__(16) float g_bias[NCAT];
__device__ int g_counts[N_NODES];
__device__ int g_rowoff[N_NODES + 1];
__device__ int g_cursor[N_NODES];
__device__ int g_csrsrc[N_EDGES];

// ---------------- CSR build (edge_index is int32) ----------------
__global__ void zero_counts_kernel() {
    int i = blockIdx.x * blockDim.x + threadIdx.x;
    if (i < N_NODES) g_counts[i] = 0;
}
__global__ void count_kernel(const int* __restrict__ ei) {
    int e = blockIdx.x * blockDim.x + threadIdx.x;
    if (e < N_EDGES) atomicAdd(&g_counts[ei[N_EDGES + e]], 1);
}
__global__ void scan_kernel() {
    __shared__ int sums[1024];
    int tid = threadIdx.x;
    const int chunk = (N_NODES + 1023) / 1024;
    int begin = tid * chunk;
    int end = begin + chunk; if (end > N_NODES) end = N_NODES;
    int s = 0;
    for (int i = begin; i < end; i++) s += g_counts[i];
    sums[tid] = s;
    __syncthreads();
    for (int off = 1; off < 1024; off <<= 1) {
        int v = (tid >= off) ? sums[tid - off] : 0;
        __syncthreads();
        sums[tid] += v;
        __syncthreads();
    }
    int run = (tid == 0) ? 0 : sums[tid - 1];
    for (int i = begin; i < end; i++) {
        g_rowoff[i] = run;
        g_cursor[i] = run;
        run += g_counts[i];
    }
    if (tid == 1023) g_rowoff[N_NODES] = run;
}
__global__ void scatter_kernel(const int* __restrict__ ei) {
    int e = blockIdx.x * blockDim.x + threadIdx.x;
    if (e < N_EDGES) {
        int pos = atomicAdd(&g_cursor[ei[N_EDGES + e]], 1);
        g_csrsrc[pos] = ei[e];
    }
}

// ---------------- weight prep: B[n][k] = W[k][n], bf16 hi/lo + bias ----------------
__global__ void convert_w_kernel(const float* __restrict__ W0, const float* __restrict__ W1,
                                 const float* __restrict__ W2, const float* __restrict__ W3,
                                 const float* __restrict__ b0, const float* __restrict__ b1,
                                 const float* __restrict__ b2, const float* __restrict__ b3) {
    int i = blockIdx.x * blockDim.x + threadIdx.x;   // over 512*128
    if (i >= NCAT * FEAT) return;
    int n = i >> 7, k = i & 127;
    int widx = n >> 7, ncol = n & 127;
    const float* W = (widx == 0) ? W0 : (widx == 1) ? W1 : (widx == 2) ? W2 : W3;
    float w = W[k * 128 + ncol];
    __nv_bfloat16 h = __float2bfloat16_rn(w);
    g_wbh[i] = h;
    g_wbl[i] = __float2bfloat16_rn(w - __bfloat162float(h));
    if (i < NCAT) {
        const float* B = (i < 128) ? b0 : (i < 256) ? b1 : (i < 384) ? b2 : b3;
        g_bias[i] = B[i & 127];
    }
}

// ---------------- bf16 mma.sync GEMM with A-reuse over 4 output blocks ----------------
__device__ __forceinline__ void mma16816(float c[4], uint32_t a0, uint32_t a1, uint32_t a2,
                                         uint32_t a3, uint32_t b0, uint32_t b1) {
    asm volatile(
        "mma.sync.aligned.m16n8k16.row.col.f32.bf16.bf16.f32 "
        "{%0,%1,%2,%3}, {%4,%5,%6,%7}, {%8,%9}, {%0,%1,%2,%3};"
        : "+f"(c[0]), "+f"(c[1]), "+f"(c[2]), "+f"(c[3])
        : "r"(a0), "r"(a1), "r"(a2), "r"(a3), "r"(b0), "r"(b1));
}
__device__ __forceinline__ uint32_t smem_u32(const void* p) {
    uint32_t a;
    asm("{ .reg .u64 t; cvta.to.shared.u64 t, %1; cvt.u32.u64 %0, t; }" : "=r"(a) : "l"(p));
    return a;
}
__device__ __forceinline__ void cp16(uint32_t s, const void* g) {
    asm volatile("cp.async.ca.shared.global [%0], [%1], 16;" :: "r"(s), "l"(g));
}
#define CP_COMMIT() asm volatile("cp.async.commit_group;" ::: "memory")
#define CP_WAIT(n)  asm volatile("cp.async.wait_group %0;" :: "n"(n) : "memory")

#define SM_TILE (128 * PAD_K)   // bf16 elements per tile
#define SMEM_BYTES (6 * SM_TILE * 2)   // [Ah | Al | Bh0 | Bl0 | Bh1 | Bl1]

__device__ __forceinline__ void load_B(int nblk, int buf, uint32_t sb, int tid) {
    uint32_t bh = sb + (2 + 2 * buf) * SM_TILE * 2;
    uint32_t bl = bh + SM_TILE * 2;
    const __nv_bfloat16* gh = g_wbh + nblk * 128 * FEAT;
    const __nv_bfloat16* gl = g_wbl + nblk * 128 * FEAT;
#pragma unroll
    for (int it = 0; it < 8; it++) {
        int p = tid + 256 * it;          // 0..2047
        int row = p >> 4, k8 = p & 15;
        uint32_t so = (uint32_t)(row * PAD_K + k8 * 8) * 2;
        cp16(bh + so, gh + p * 8);
        cp16(bl + so, gl + p * 8);
    }
}

template <int SRC>
__global__ void __launch_bounds__(256, 1)
gemm_mma_kernel(const float* __restrict__ Xin) {
    extern __shared__ __nv_bfloat16 sm[];
    __nv_bfloat16* sAh = sm;
    __nv_bfloat16* sAl = sm + SM_TILE;
    uint32_t sb = smem_u32(sm);

    const float* X = (SRC == 0) ? Xin : (const float*)g_h1;
    int tid = threadIdx.x;
    int wid = tid >> 5, lane = tid & 31;
    int m0 = blockIdx.x * 128;

    load_B(0, 0, sb, tid);
    CP_COMMIT();

    // A: load fp32, split to bf16 hi/lo in registers, stage to smem
    const float4* X4 = (const float4*)X;
#pragma unroll
    for (int it = 0; it < 16; it++) {
        int q = tid + 256 * it;          // 0..4095
        int row = q >> 5, c4 = q & 31;
        int rg = m0 + row; if (rg > N_NODES - 1) rg = N_NODES - 1;
        float4 f = X4[(size_t)rg * 32 + c4];
        __nv_bfloat16 h0 = __float2bfloat16_rn(f.x);
        __nv_bfloat16 h1 = __float2bfloat16_rn(f.y);
        __nv_bfloat16 h2 = __float2bfloat16_rn(f.z);
        __nv_bfloat16 h3 = __float2bfloat16_rn(f.w);
        __nv_bfloat16 l0 = __float2bfloat16_rn(f.x - __bfloat162float(h0));
        __nv_bfloat16 l1 = __float2bfloat16_rn(f.y - __bfloat162float(h1));
        __nv_bfloat16 l2 = __float2bfloat16_rn(f.z - __bfloat162float(h2));
        __nv_bfloat16 l3 = __float2bfloat16_rn(f.w - __bfloat162float(h3));
        __nv_bfloat162 hp0(h0, h1), hp1(h2, h3), lp0(l0, l1), lp1(l2, l3);
        uint2 hv, lv;
        hv.x = *(uint32_t*)&hp0; hv.y = *(uint32_t*)&hp1;
        lv.x = *(uint32_t*)&lp0; lv.y = *(uint32_t*)&lp1;
        int eo = row * PAD_K + c4 * 4;
        *(uint2*)&sAh[eo] = hv;
        *(uint2*)&sAl[eo] = lv;
    }

    load_B(1, 1, sb, tid);
    CP_COMMIT();
    CP_WAIT(1);
    __syncthreads();

    int wm = wid >> 2, wn = wid & 3;
    int qid = lane >> 2, tq = (lane & 3) * 2;

    for (int nblk = 0; nblk < 4; nblk++) {
        __nv_bfloat16* sBh = sm + (2 + 2 * (nblk & 1)) * SM_TILE;
        __nv_bfloat16* sBl = sBh + SM_TILE;

        float c[4][4][4];
#pragma unroll
        for (int i = 0; i < 4; i++)
#pragma unroll
            for (int j = 0; j < 4; j++)
#pragma unroll
                for (int r = 0; r < 4; r++) c[i][j][r] = 0.f;

#pragma unroll
        for (int ks = 0; ks < 8; ks++) {
            int kb = ks * 16;
            uint32_t ah[4][4], al[4][4], bh[4][2], bl[4][2];
#pragma unroll
            for (int i = 0; i < 4; i++) {
                int r0 = (wm * 64 + i * 16 + qid) * PAD_K;
                int r8 = r0 + 8 * PAD_K;
                ah[i][0] = *(const uint32_t*)&sAh[r0 + kb + tq];
                ah[i][1] = *(const uint32_t*)&sAh[r8 + kb + tq];
                ah[i][2] = *(const uint32_t*)&sAh[r0 + kb + 8 + tq];
                ah[i][3] = *(const uint32_t*)&sAh[r8 + kb + 8 + tq];
                al[i][0] = *(const uint32_t*)&sAl[r0 + kb + tq];
                al[i][1] = *(const uint32_t*)&sAl[r8 + kb + tq];
                al[i][2] = *(const uint32_t*)&sAl[r0 + kb + 8 + tq];
                al[i][3] = *(const uint32_t*)&sAl[r8 + kb + 8 + tq];
            }
#pragma unroll
            for (int j = 0; j < 4; j++) {
                int n0 = (wn * 32 + j * 8 + qid) * PAD_K;
                bh[j][0] = *(const uint32_t*)&sBh[n0 + kb + tq];
                bh[j][1] = *(const uint32_t*)&sBh[n0 + kb + 8 + tq];
                bl[j][0] = *(const uint32_t*)&sBl[n0 + kb + tq];
                bl[j][1] = *(const uint32_t*)&sBl[n0 + kb + 8 + tq];
            }
#pragma unroll
            for (int i = 0; i < 4; i++)
#pragma unroll
                for (int j = 0; j < 4; j++) {
                    mma16816(c[i][j], ah[i][0], ah[i][1], ah[i][2], ah[i][3], bh[j][0], bh[j][1]);
                    mma16816(c[i][j], al[i][0], al[i][1], al[i][2], al[i][3], bh[j][0], bh[j][1]);
                    mma16816(c[i][j], ah[i][0], ah[i][1], ah[i][2], ah[i][3], bl[j][0], bl[j][1]);
                }
        }

        // epilogue routing:
        //   q (0), sk (3) -> fp32 g_qsk at col offset 0 / 128
        //   k (1), v (2)  -> fp16 g_kvh interleaved: elem = row*256 + (c>>2)*8 + sel*4 + (c&3)
        bool is_qsk = (nblk == 0 || nblk == 3);
        int colofs = (nblk == 3) ? 128 : 0;
        int sel = (nblk == 2) ? 1 : 0;
#pragma unroll
        for (int i = 0; i < 4; i++) {
            int row = m0 + wm * 64 + i * 16 + qid;
#pragma unroll
            for (int j = 0; j < 4; j++) {
                int col = wn * 32 + j * 8 + tq;   // even, pair (col, col+1) in same 4-chunk
                float2 bb = *(const float2*)&g_bias[nblk * 128 + col];
                float2 o0 = {c[i][j][0] + bb.x, c[i][j][1] + bb.y};
                float2 o1 = {c[i][j][2] + bb.x, c[i][j][3] + bb.y};
                if (is_qsk) {
                    if (row < N_NODES)
                        *(float2*)&g_qsk[(size_t)row * 256 + colofs + col] = o0;
                    if (row + 8 < N_NODES)
                        *(float2*)&g_qsk[(size_t)(row + 8) * 256 + colofs + col] = o1;
                } else {
                    uint32_t eo = (uint32_t)((col >> 2) * 8 + sel * 4 + (col & 3));
                    if (row < N_NODES) {
                        __half2 p = __floats2half2_rn(o0.x, o0.y);
                        *(__half2*)&g_kvh[(size_t)row * 256 + eo] = p;
                    }
                    if (row + 8 < N_NODES) {
                        __half2 p = __floats2half2_rn(o1.x, o1.y);
                        *(__half2*)&g_kvh[(size_t)(row + 8) * 256 + eo] = p;
                    }
                }
            }
        }

        if (nblk < 3) {
            __syncthreads();
            if (nblk + 2 <= 3) {
                load_B(nblk + 2, nblk & 1, sb, tid);
                CP_COMMIT();
                CP_WAIT(1);
            } else {
                CP_WAIT(0);
            }
            __syncthreads();
        }
    }
}

// ---------------- attention core: one LDG.128/edge (fp16 k4|v4), 4-edge pipeline ----------------
#define EDGE_DOT(cc, dd)                                                                   \
    {                                                                                      \
        float2 ka = __half22float2(*(__half2*)&cc.x);                                      \
        float2 kb = __half22float2(*(__half2*)&cc.y);                                      \
        dd = fmaf(qv.x, ka.x, fmaf(qv.y, ka.y, fmaf(qv.z, kb.x, qv.w * kb.y)));            \
    }
#define EDGE_ACC(cc, ww, ss, aa)                                                           \
    {                                                                                      \
        float2 va = __half22float2(*(__half2*)&cc.z);                                      \
        float2 vb = __half22float2(*(__half2*)&cc.w);                                      \
        ss += ww;                                                                          \
        aa.x = fmaf(ww, va.x, aa.x);                                                       \
        aa.y = fmaf(ww, va.y, aa.y);                                                       \
        aa.z = fmaf(ww, vb.x, aa.z);                                                       \
        aa.w = fmaf(ww, vb.y, aa.w);                                                       \
    }

__device__ __forceinline__ float4 attn_node(int node, int lane) {
    const float4* qsk = (const float4*)g_qsk;        // 64 float4 per row
    const uint4*  kvh = (const uint4*)g_kvh;         // 32 uint4 per row: [k4(fp16)|v4(fp16)]

    float4 qv = qsk[(size_t)node * 64 + lane];
    qv.x *= 0.125f; qv.y *= 0.125f; qv.z *= 0.125f; qv.w *= 0.125f;  // 1/sqrt(64)

    int e0 = g_rowoff[node];
    int e1 = g_rowoff[node + 1];

    float sA = 0.f, sB = 0.f, sC = 0.f, sD = 0.f;
    float4 aA = {0, 0, 0, 0}, aB = {0, 0, 0, 0}, aC = {0, 0, 0, 0}, aD = {0, 0, 0, 0};

    int e = e0;
    for (; e + 4 <= e1; e += 4) {
        int s0 = g_csrsrc[e];
        int s1 = g_csrsrc[e + 1];
        int s2 = g_csrsrc[e + 2];
        int s3 = g_csrsrc[e + 3];
        uint4 c0 = kvh[(size_t)s0 * 32 + lane];
        uint4 c1 = kvh[(size_t)s1 * 32 + lane];
        uint4 c2 = kvh[(size_t)s2 * 32 + lane];
        uint4 c3 = kvh[(size_t)s3 * 32 + lane];
        float d0, d1, d2, d3;
        EDGE_DOT(c0, d0); EDGE_DOT(c1, d1); EDGE_DOT(c2, d2); EDGE_DOT(c3, d3);
        d0 += __shfl_xor_sync(0xffffffffu, d0, 8);
        d1 += __shfl_xor_sync(0xffffffffu, d1, 8);
        d2 += __shfl_xor_sync(0xffffffffu, d2, 8);
        d3 += __shfl_xor_sync(0xffffffffu, d3, 8);
        d0 += __shfl_xor_sync(0xffffffffu, d0, 4);
        d1 += __shfl_xor_sync(0xffffffffu, d1, 4);
        d2 += __shfl_xor_sync(0xffffffffu, d2, 4);
        d3 += __shfl_xor_sync(0xffffffffu, d3, 4);
        d0 += __shfl_xor_sync(0xffffffffu, d0, 2);
        d1 += __shfl_xor_sync(0xffffffffu, d1, 2);
        d2 += __shfl_xor_sync(0xffffffffu, d2, 2);
        d3 += __shfl_xor_sync(0xffffffffu, d3, 2);
        d0 += __shfl_xor_sync(0xffffffffu, d0, 1);
        d1 += __shfl_xor_sync(0xffffffffu, d1, 1);
        d2 += __shfl_xor_sync(0xffffffffu, d2, 1);
        d3 += __shfl_xor_sync(0xffffffffu, d3, 1);
        float w0 = __expf(d0);
        float w1 = __expf(d1);
        float w2 = __expf(d2);
        float w3 = __expf(d3);
        EDGE_ACC(c0, w0, sA, aA);
        EDGE_ACC(c1, w1, sB, aB);
        EDGE_ACC(c2, w2, sC, aC);
        EDGE_ACC(c3, w3, sD, aD);
    }
    for (; e < e1; e++) {
        int s0 = g_csrsrc[e];
        uint4 c0 = kvh[(size_t)s0 * 32 + lane];
        float d0;
        EDGE_DOT(c0, d0);
        d0 += __shfl_xor_sync(0xffffffffu, d0, 8);
        d0 += __shfl_xor_sync(0xffffffffu, d0, 4);
        d0 += __shfl_xor_sync(0xffffffffu, d0, 2);
        d0 += __shfl_xor_sync(0xffffffffu, d0, 1);
        float w0 = __expf(d0);
        EDGE_ACC(c0, w0, sA, aA);
    }

    float s = (sA + sB) + (sC + sD);
    float4 acc;
    acc.x = (aA.x + aB.x) + (aC.x + aD.x);
    acc.y = (aA.y + aB.y) + (aC.y + aD.y);
    acc.z = (aA.z + aB.z) + (aC.z + aD.z);
    acc.w = (aA.w + aB.w) + (aC.w + aD.w);

    float inv = 1.0f / fmaxf(s, 1e-16f);
    float4 sk = qsk[(size_t)node * 64 + 32 + lane];
    float4 o;
    o.x = fmaf(acc.x, inv, sk.x);
    o.y = fmaf(acc.y, inv, sk.y);
    o.z = fmaf(acc.z, inv, sk.z);
    o.w = fmaf(acc.w, inv, sk.w);
    return o;
}

// Layer 1: attn + ELU -> g_h1 (fp32; layer-2 GEMM converts inline)
__global__ void attn1_kernel() {
    int node = blockIdx.x * 8 + (threadIdx.x >> 5);   // N_NODES % 8 == 0
    int lane = threadIdx.x & 31;
    float4 o = attn_node(node, lane);
    o.x = (o.x > 0.f) ? o.x : expm1f(o.x);
    o.y = (o.y > 0.f) ? o.y : expm1f(o.y);
    o.z = (o.z > 0.f) ? o.z : expm1f(o.z);
    o.w = (o.w > 0.f) ? o.w : expm1f(o.w);
    ((float4*)g_h1)[(size_t)node * 32 + lane] = o;
}

// Layer 2: attn -> g_h2
__global__ void attn2_kernel() {
    int node = blockIdx.x * 8 + (threadIdx.x >> 5);
    int lane = threadIdx.x & 31;
    float4 o = attn_node(node, lane);
    ((float4*)g_h2)[(size_t)node * 32 + lane] = o;
}

// ---------------- classifier: out = g_h2 @ Wc + bc  (128 -> 40) ----------------
__global__ void classifier_kernel(const float* __restrict__ Wc,
                                  const float* __restrict__ bc,
                                  float* __restrict__ out) {
    const float* H = (const float*)g_h2;
    __shared__ float Ws[128 * 40];
    for (int i = threadIdx.x; i < 128 * 40; i += 256) Ws[i] = Wc[i];
    __syncthreads();

    int cg = threadIdx.x & 7;
    int nr = threadIdx.x >> 3;
    int n0 = blockIdx.x * 64 + nr * 2;

    int r0 = (n0     < N_NODES) ? n0     : N_NODES - 1;
    int r1 = (n0 + 1 < N_NODES) ? n0 + 1 : N_NODES - 1;
    const float* h0p = H + (size_t)r0 * 128;
    const float* h1p = H + (size_t)r1 * 128;

    float a0[5] = {0, 0, 0, 0, 0};
    float a1[5] = {0, 0, 0, 0, 0};
#pragma unroll 4
    for (int k = 0; k < 128; k++) {
        float h0 = h0p[k];
        float h1 = h1p[k];
#pragma unroll
        for (int j = 0; j < 5; j++) {
            float w = Ws[k * 40 + cg * 5 + j];
            a0[j] = fmaf(h0, w, a0[j]);
            a1[j] = fmaf(h1, w, a1[j]);
        }
    }
    if (n0 < N_NODES)
#pragma unroll
        for (int j = 0; j < 5; j++) out[(size_t)n0 * 40 + cg * 5 + j] = a0[j] + bc[cg * 5 + j];
    if (n0 + 1 < N_NODES)
#pragma unroll
        for (int j = 0; j < 5; j++) out[(size_t)(n0 + 1) * 40 + cg * 5 + j] = a1[j] + bc[cg * 5 + j];
}

// ---------------- launch ----------------
extern "C" void kernel_launch(void* const* d_in, const int* in_sizes, int n_in,
                              void* d_out, int out_size) {
    const float* x   = (const float*)d_in[0];
    const int*   ei  = (const int*)d_in[1];   // int32 (JAX x64-disabled)
    const float* Wq1 = (const float*)d_in[2];  const float* bq1 = (const float*)d_in[3];
    const float* Wk1 = (const float*)d_in[4];  const float* bk1 = (const float*)d_in[5];
    const float* Wv1 = (const float*)d_in[6];  const float* bv1 = (const float*)d_in[7];
    const float* Ws1 = (const float*)d_in[8];  const float* bs1 = (const float*)d_in[9];
    const float* Wq2 = (const float*)d_in[10]; const float* bq2 = (const float*)d_in[11];
    const float* Wk2 = (const float*)d_in[12]; const float* bk2 = (const float*)d_in[13];
    const float* Wv2 = (const float*)d_in[14]; const float* bv2 = (const float*)d_in[15];
    const float* Ws2 = (const float*)d_in[16]; const float* bs2 = (const float*)d_in[17];
    const float* Wc  = (const float*)d_in[18]; const float* bc  = (const float*)d_in[19];
    float* out = (float*)d_out;

    static int configured = 0;
    if (!configured) {
        cudaFuncSetAttribute(gemm_mma_kernel<0>, cudaFuncAttributeMaxDynamicSharedMemorySize,
                             SMEM_BYTES);
        cudaFuncSetAttribute(gemm_mma_kernel<1>, cudaFuncAttributeMaxDynamicSharedMemorySize,
                             SMEM_BYTES);
        configured = 1;
    }

    // CSR build (shared by both layers)
    zero_counts_kernel<<<(N_NODES + 255) / 256, 256>>>();
    count_kernel<<<(N_EDGES + 255) / 256, 256>>>(ei);
    scan_kernel<<<1, 1024>>>();
    scatter_kernel<<<(N_EDGES + 255) / 256, 256>>>(ei);

    int nattn = N_NODES / 8;   // 12500 full blocks

    // Layer 1
    convert_w_kernel<<<(NCAT * FEAT + 255) / 256, 256>>>(Wq1, Wk1, Wv1, Ws1, bq1, bk1, bv1, bs1);
    gemm_mma_kernel<0><<<M_TILES, 256, SMEM_BYTES>>>(x);
    attn1_kernel<<<nattn, 256>>>();

    // Layer 2
    convert_w_kernel<<<(NCAT * FEAT + 255) / 256, 256>>>(Wq2, Wk2, Wv2, Ws2, bq2, bk2, bv2, bs2);
    gemm_mma_kernel<1><<<M_TILES, 256, SMEM_BYTES>>>(nullptr);
    attn2_kernel<<<nattn, 256>>>();

    // Classifier
    classifier_kernel<<<(N_NODES + 63) / 64, 256>>>(Wc, bc, out);
}

// round 13
// speedup vs baseline: 1.0908x; 1.0908x over previous
#include <cuda_runtime.h>
#include <cuda_bf16.h>
#include <cuda_fp16.h>
#include <cstdint>

#define N_NODES 100000
#define N_EDGES 1600000
#define FEAT 128
#define NCAT 512
#define M_TILES ((N_NODES + 127) / 128)
#define PAD_K 136   // bf16 elements per SMEM row (272B: 16B-aligned, conflict-free frags)

// ---------------- scratch (static __device__, no allocation) ----------------
__device__ __align__(16) float g_qsk[(size_t)N_NODES * 256];   // [node][q(128)|sk(128)] fp32, streamed
__device__ __align__(16) __half g_kvh[(size_t)N_NODES * 256];  // [node][32 x (k4|v4)] fp16, gather set (51MB)
__device__ __align__(16) float g_h1[N_NODES * FEAT];
__device__ __align__(16) float g_h2[N_NODES * FEAT];
__device__ __align__(16) __nv_bfloat16 g_wbh[NCAT * FEAT];  // B[n][k] = W[k][n], hi
__device__ __align__(16) __nv_bfloat16 g_wbl[NCAT * FEAT];  // lo
__device__ __align__(16) float g_bias[NCAT];
__device__ int g_counts[N_NODES];
__device__ int g_rowoff[N_NODES + 1];
__device__ int g_cursor[N_NODES];
__device__ int g_csrsrc[N_EDGES];

// ---------------- CSR build (edge_index is int32) ----------------
__global__ void zero_counts_kernel() {
    int i = blockIdx.x * blockDim.x + threadIdx.x;
    if (i < N_NODES) g_counts[i] = 0;
}
__global__ void count_kernel(const int* __restrict__ ei) {
    int e = blockIdx.x * blockDim.x + threadIdx.x;
    if (e < N_EDGES) atomicAdd(&g_counts[ei[N_EDGES + e]], 1);
}
__global__ void scan_kernel() {
    __shared__ int sums[1024];
    int tid = threadIdx.x;
    const int chunk = (N_NODES + 1023) / 1024;
    int begin = tid * chunk;
    int end = begin + chunk; if (end > N_NODES) end = N_NODES;
    int s = 0;
    for (int i = begin; i < end; i++) s += g_counts[i];
    sums[tid] = s;
    __syncthreads();
    for (int off = 1; off < 1024; off <<= 1) {
        int v = (tid >= off) ? sums[tid - off] : 0;
        __syncthreads();
        sums[tid] += v;
        __syncthreads();
    }
    int run = (tid == 0) ? 0 : sums[tid - 1];
    for (int i = begin; i < end; i++) {
        g_rowoff[i] = run;
        g_cursor[i] = run;
        run += g_counts[i];
    }
    if (tid == 1023) g_rowoff[N_NODES] = run;
}
__global__ void scatter_kernel(const int* __restrict__ ei) {
    int e = blockIdx.x * blockDim.x + threadIdx.x;
    if (e < N_EDGES) {
        int pos = atomicAdd(&g_cursor[ei[N_EDGES + e]], 1);
        g_csrsrc[pos] = ei[e];
    }
}

// ---------------- weight prep: B[n][k] = W[k][n], bf16 hi/lo + bias ----------------
__global__ void convert_w_kernel(const float* __restrict__ W0, const float* __restrict__ W1,
                                 const float* __restrict__ W2, const float* __restrict__ W3,
                                 const float* __restrict__ b0, const float* __restrict__ b1,
                                 const float* __restrict__ b2, const float* __restrict__ b3) {
    int i = blockIdx.x * blockDim.x + threadIdx.x;   // over 512*128
    if (i >= NCAT * FEAT) return;
    int n = i >> 7, k = i & 127;
    int widx = n >> 7, ncol = n & 127;
    const float* W = (widx == 0) ? W0 : (widx == 1) ? W1 : (widx == 2) ? W2 : W3;
    float w = W[k * 128 + ncol];
    __nv_bfloat16 h = __float2bfloat16_rn(w);
    g_wbh[i] = h;
    g_wbl[i] = __float2bfloat16_rn(w - __bfloat162float(h));
    if (i < NCAT) {
        const float* B = (i < 128) ? b0 : (i < 256) ? b1 : (i < 384) ? b2 : b3;
        g_bias[i] = B[i & 127];
    }
}

// ---------------- bf16 mma.sync GEMM with A-reuse over 4 output blocks ----------------
__device__ __forceinline__ void mma16816(float c[4], uint32_t a0, uint32_t a1, uint32_t a2,
                                         uint32_t a3, uint32_t b0, uint32_t b1) {
    asm volatile(
        "mma.sync.aligned.m16n8k16.row.col.f32.bf16.bf16.f32 "
        "{%0,%1,%2,%3}, {%4,%5,%6,%7}, {%8,%9}, {%0,%1,%2,%3};"
        : "+f"(c[0]), "+f"(c[1]), "+f"(c[2]), "+f"(c[3])
        : "r"(a0), "r"(a1), "r"(a2), "r"(a3), "r"(b0), "r"(b1));
}
__device__ __forceinline__ uint32_t smem_u32(const void* p) {
    uint32_t a;
    asm("{ .reg .u64 t; cvta.to.shared.u64 t, %1; cvt.u32.u64 %0, t; }" : "=r"(a) : "l"(p));
    return a;
}
__device__ __forceinline__ void cp16(uint32_t s, const void* g) {
    asm volatile("cp.async.ca.shared.global [%0], [%1], 16;" :: "r"(s), "l"(g));
}
#define CP_COMMIT() asm volatile("cp.async.commit_group;" ::: "memory")
#define CP_WAIT(n)  asm volatile("cp.async.wait_group %0;" :: "n"(n) : "memory")

#define SM_TILE (128 * PAD_K)   // bf16 elements per tile
#define SMEM_BYTES (6 * SM_TILE * 2)   // [Ah | Al | Bh0 | Bl0 | Bh1 | Bl1]

__device__ __forceinline__ void load_B(int nblk, int buf, uint32_t sb, int tid) {
    uint32_t bh = sb + (2 + 2 * buf) * SM_TILE * 2;
    uint32_t bl = bh + SM_TILE * 2;
    const __nv_bfloat16* gh = g_wbh + nblk * 128 * FEAT;
    const __nv_bfloat16* gl = g_wbl + nblk * 128 * FEAT;
#pragma unroll
    for (int it = 0; it < 8; it++) {
        int p = tid + 256 * it;          // 0..2047
        int row = p >> 4, k8 = p & 15;
        uint32_t so = (uint32_t)(row * PAD_K + k8 * 8) * 2;
        cp16(bh + so, gh + p * 8);
        cp16(bl + so, gl + p * 8);
    }
}

template <int SRC>
__global__ void __launch_bounds__(256, 1)
gemm_mma_kernel(const float* __restrict__ Xin) {
    extern __shared__ __nv_bfloat16 sm[];
    __nv_bfloat16* sAh = sm;
    __nv_bfloat16* sAl = sm + SM_TILE;
    uint32_t sb = smem_u32(sm);

    const float* X = (SRC == 0) ? Xin : (const float*)g_h1;
    int tid = threadIdx.x;
    int wid = tid >> 5, lane = tid & 31;
    int m0 = blockIdx.x * 128;

    load_B(0, 0, sb, tid);
    CP_COMMIT();

    // A: load fp32, split to bf16 hi/lo in registers, stage to smem
    const float4* X4 = (const float4*)X;
#pragma unroll
    for (int it = 0; it < 16; it++) {
        int q = tid + 256 * it;          // 0..4095
        int row = q >> 5, c4 = q & 31;
        int rg = m0 + row; if (rg > N_NODES - 1) rg = N_NODES - 1;
        float4 f = X4[(size_t)rg * 32 + c4];
        __nv_bfloat16 h0 = __float2bfloat16_rn(f.x);
        __nv_bfloat16 h1 = __float2bfloat16_rn(f.y);
        __nv_bfloat16 h2 = __float2bfloat16_rn(f.z);
        __nv_bfloat16 h3 = __float2bfloat16_rn(f.w);
        __nv_bfloat16 l0 = __float2bfloat16_rn(f.x - __bfloat162float(h0));
        __nv_bfloat16 l1 = __float2bfloat16_rn(f.y - __bfloat162float(h1));
        __nv_bfloat16 l2 = __float2bfloat16_rn(f.z - __bfloat162float(h2));
        __nv_bfloat16 l3 = __float2bfloat16_rn(f.w - __bfloat162float(h3));
        __nv_bfloat162 hp0(h0, h1), hp1(h2, h3), lp0(l0, l1), lp1(l2, l3);
        uint2 hv, lv;
        hv.x = *(uint32_t*)&hp0; hv.y = *(uint32_t*)&hp1;
        lv.x = *(uint32_t*)&lp0; lv.y = *(uint32_t*)&lp1;
        int eo = row * PAD_K + c4 * 4;
        *(uint2*)&sAh[eo] = hv;
        *(uint2*)&sAl[eo] = lv;
    }

    load_B(1, 1, sb, tid);
    CP_COMMIT();
    CP_WAIT(1);
    __syncthreads();

    int wm = wid >> 2, wn = wid & 3;
    int qid = lane >> 2, tq = (lane & 3) * 2;

    for (int nblk = 0; nblk < 4; nblk++) {
        __nv_bfloat16* sBh = sm + (2 + 2 * (nblk & 1)) * SM_TILE;
        __nv_bfloat16* sBl = sBh + SM_TILE;

        float c[4][4][4];
#pragma unroll
        for (int i = 0; i < 4; i++)
#pragma unroll
            for (int j = 0; j < 4; j++)
#pragma unroll
                for (int r = 0; r < 4; r++) c[i][j][r] = 0.f;

#pragma unroll
        for (int ks = 0; ks < 8; ks++) {
            int kb = ks * 16;
            uint32_t ah[4][4], al[4][4], bh[4][2], bl[4][2];
#pragma unroll
            for (int i = 0; i < 4; i++) {
                int r0 = (wm * 64 + i * 16 + qid) * PAD_K;
                int r8 = r0 + 8 * PAD_K;
                ah[i][0] = *(const uint32_t*)&sAh[r0 + kb + tq];
                ah[i][1] = *(const uint32_t*)&sAh[r8 + kb + tq];
                ah[i][2] = *(const uint32_t*)&sAh[r0 + kb + 8 + tq];
                ah[i][3] = *(const uint32_t*)&sAh[r8 + kb + 8 + tq];
                al[i][0] = *(const uint32_t*)&sAl[r0 + kb + tq];
                al[i][1] = *(const uint32_t*)&sAl[r8 + kb + tq];
                al[i][2] = *(const uint32_t*)&sAl[r0 + kb + 8 + tq];
                al[i][3] = *(const uint32_t*)&sAl[r8 + kb + 8 + tq];
            }
#pragma unroll
            for (int j = 0; j < 4; j++) {
                int n0 = (wn * 32 + j * 8 + qid) * PAD_K;
                bh[j][0] = *(const uint32_t*)&sBh[n0 + kb + tq];
                bh[j][1] = *(const uint32_t*)&sBh[n0 + kb + 8 + tq];
                bl[j][0] = *(const uint32_t*)&sBl[n0 + kb + tq];
                bl[j][1] = *(const uint32_t*)&sBl[n0 + kb + 8 + tq];
            }
#pragma unroll
            for (int i = 0; i < 4; i++)
#pragma unroll
                for (int j = 0; j < 4; j++) {
                    mma16816(c[i][j], ah[i][0], ah[i][1], ah[i][2], ah[i][3], bh[j][0], bh[j][1]);
                    mma16816(c[i][j], al[i][0], al[i][1], al[i][2], al[i][3], bh[j][0], bh[j][1]);
                    mma16816(c[i][j], ah[i][0], ah[i][1], ah[i][2], ah[i][3], bl[j][0], bl[j][1]);
                }
        }

        // epilogue routing:
        //   q (0), sk (3) -> fp32 g_qsk at col offset 0 / 128
        //   k (1), v (2)  -> fp16 g_kvh interleaved: elem = row*256 + (c>>2)*8 + sel*4 + (c&3)
        bool is_qsk = (nblk == 0 || nblk == 3);
        int colofs = (nblk == 3) ? 128 : 0;
        int sel = (nblk == 2) ? 1 : 0;
#pragma unroll
        for (int i = 0; i < 4; i++) {
            int row = m0 + wm * 64 + i * 16 + qid;
#pragma unroll
            for (int j = 0; j < 4; j++) {
                int col = wn * 32 + j * 8 + tq;   // even, pair (col, col+1) in same 4-chunk
                float2 bb = *(const float2*)&g_bias[nblk * 128 + col];
                float2 o0 = {c[i][j][0] + bb.x, c[i][j][1] + bb.y};
                float2 o1 = {c[i][j][2] + bb.x, c[i][j][3] + bb.y};
                if (is_qsk) {
                    if (row < N_NODES)
                        *(float2*)&g_qsk[(size_t)row * 256 + colofs + col] = o0;
                    if (row + 8 < N_NODES)
                        *(float2*)&g_qsk[(size_t)(row + 8) * 256 + colofs + col] = o1;
                } else {
                    uint32_t eo = (uint32_t)((col >> 2) * 8 + sel * 4 + (col & 3));
                    if (row < N_NODES) {
                        __half2 p = __floats2half2_rn(o0.x, o0.y);
                        *(__half2*)&g_kvh[(size_t)row * 256 + eo] = p;
                    }
                    if (row + 8 < N_NODES) {
                        __half2 p = __floats2half2_rn(o1.x, o1.y);
                        *(__half2*)&g_kvh[(size_t)(row + 8) * 256 + eo] = p;
                    }
                }
            }
        }

        if (nblk < 3) {
            __syncthreads();
            if (nblk + 2 <= 3) {
                load_B(nblk + 2, nblk & 1, sb, tid);
                CP_COMMIT();
                CP_WAIT(1);
            } else {
                CP_WAIT(0);
            }
            __syncthreads();
        }
    }
}

// ---------------- attention core: one LDG.128/edge (fp16 k4|v4), 2-edge pipeline ----------------
__device__ __forceinline__ float4 attn_node(int node, int lane) {
    const float4* qsk = (const float4*)g_qsk;        // 64 float4 per row
    const uint4*  kvh = (const uint4*)g_kvh;         // 32 uint4 per row: [k4(fp16)|v4(fp16)]

    float4 qv = qsk[(size_t)node * 64 + lane];
    qv.x *= 0.125f; qv.y *= 0.125f; qv.z *= 0.125f; qv.w *= 0.125f;  // 1/sqrt(64)

    int e0 = g_rowoff[node];
    int e1 = g_rowoff[node + 1];

    float sA = 0.f, sB = 0.f;
    float4 aA = {0.f, 0.f, 0.f, 0.f}, aB = {0.f, 0.f, 0.f, 0.f};

    int e = e0;
    for (; e + 2 <= e1; e += 2) {
        int s0 = g_csrsrc[e];
        int s1 = g_csrsrc[e + 1];
        uint4 c0 = kvh[(size_t)s0 * 32 + lane];
        uint4 c1 = kvh[(size_t)s1 * 32 + lane];
        float2 k0a = __half22float2(*(__half2*)&c0.x);
        float2 k0b = __half22float2(*(__half2*)&c0.y);
        float2 v0a = __half22float2(*(__half2*)&c0.z);
        float2 v0b = __half22float2(*(__half2*)&c0.w);
        float2 k1a = __half22float2(*(__half2*)&c1.x);
        float2 k1b = __half22float2(*(__half2*)&c1.y);
        float2 v1a = __half22float2(*(__half2*)&c1.z);
        float2 v1b = __half22float2(*(__half2*)&c1.w);
        float d0 = fmaf(qv.x, k0a.x, fmaf(qv.y, k0a.y, fmaf(qv.z, k0b.x, qv.w * k0b.y)));
        float d1 = fmaf(qv.x, k1a.x, fmaf(qv.y, k1a.y, fmaf(qv.z, k1b.x, qv.w * k1b.y)));
        d0 += __shfl_xor_sync(0xffffffffu, d0, 8);
        d1 += __shfl_xor_sync(0xffffffffu, d1, 8);
        d0 += __shfl_xor_sync(0xffffffffu, d0, 4);
        d1 += __shfl_xor_sync(0xffffffffu, d1, 4);
        d0 += __shfl_xor_sync(0xffffffffu, d0, 2);
        d1 += __shfl_xor_sync(0xffffffffu, d1, 2);
        d0 += __shfl_xor_sync(0xffffffffu, d0, 1);
        d1 += __shfl_xor_sync(0xffffffffu, d1, 1);
        float w0 = __expf(d0);
        float w1 = __expf(d1);
        sA += w0; sB += w1;
        aA.x = fmaf(w0, v0a.x, aA.x); aB.x = fmaf(w1, v1a.x, aB.x);
        aA.y = fmaf(w0, v0a.y, aA.y); aB.y = fmaf(w1, v1a.y, aB.y);
        aA.z = fmaf(w0, v0b.x, aA.z); aB.z = fmaf(w1, v1b.x, aB.z);
        aA.w = fmaf(w0, v0b.y, aA.w); aB.w = fmaf(w1, v1b.y, aB.w);
    }
    if (e < e1) {
        int s0 = g_csrsrc[e];
        uint4 c0 = kvh[(size_t)s0 * 32 + lane];
        float2 k0a = __half22float2(*(__half2*)&c0.x);
        float2 k0b = __half22float2(*(__half2*)&c0.y);
        float2 v0a = __half22float2(*(__half2*)&c0.z);
        float2 v0b = __half22float2(*(__half2*)&c0.w);
        float d0 = fmaf(qv.x, k0a.x, fmaf(qv.y, k0a.y, fmaf(qv.z, k0b.x, qv.w * k0b.y)));
        d0 += __shfl_xor_sync(0xffffffffu, d0, 8);
        d0 += __shfl_xor_sync(0xffffffffu, d0, 4);
        d0 += __shfl_xor_sync(0xffffffffu, d0, 2);
        d0 += __shfl_xor_sync(0xffffffffu, d0, 1);
        float w0 = __expf(d0);
        sA += w0;
        aA.x = fmaf(w0, v0a.x, aA.x);
        aA.y = fmaf(w0, v0a.y, aA.y);
        aA.z = fmaf(w0, v0b.x, aA.z);
        aA.w = fmaf(w0, v0b.y, aA.w);
    }

    float s = sA + sB;
    float inv = 1.0f / fmaxf(s, 1e-16f);
    float4 sk = qsk[(size_t)node * 64 + 32 + lane];
    float4 o;
    o.x = fmaf(aA.x + aB.x, inv, sk.x);
    o.y = fmaf(aA.y + aB.y, inv, sk.y);
    o.z = fmaf(aA.z + aB.z, inv, sk.z);
    o.w = fmaf(aA.w + aB.w, inv, sk.w);
    return o;
}

// Layer 1: attn + ELU -> g_h1 (fp32; layer-2 GEMM converts inline)
__global__ void attn1_kernel() {
    int node = blockIdx.x * 8 + (threadIdx.x >> 5);   // N_NODES % 8 == 0
    int lane = threadIdx.x & 31;
    float4 o = attn_node(node, lane);
    o.x = (o.x > 0.f) ? o.x : expm1f(o.x);
    o.y = (o.y > 0.f) ? o.y : expm1f(o.y);
    o.z = (o.z > 0.f) ? o.z : expm1f(o.z);
    o.w = (o.w > 0.f) ? o.w : expm1f(o.w);
    ((float4*)g_h1)[(size_t)node * 32 + lane] = o;
}

// Layer 2: attn -> g_h2
__global__ void attn2_kernel() {
    int node = blockIdx.x * 8 + (threadIdx.x >> 5);
    int lane = threadIdx.x & 31;
    float4 o = attn_node(node, lane);
    ((float4*)g_h2)[(size_t)node * 32 + lane] = o;
}

// ---------------- classifier: out = g_h2 @ Wc + bc  (128 -> 40) ----------------
__global__ void classifier_kernel(const float* __restrict__ Wc,
                                  const float* __restrict__ bc,
                                  float* __restrict__ out) {
    const float* H = (const float*)g_h2;
    __shared__ float Ws[128 * 40];
    for (int i = threadIdx.x; i < 128 * 40; i += 256) Ws[i] = Wc[i];
    __syncthreads();

    int cg = threadIdx.x & 7;
    int nr = threadIdx.x >> 3;
    int n0 = blockIdx.x * 64 + nr * 2;

    int r0 = (n0     < N_NODES) ? n0     : N_NODES - 1;
    int r1 = (n0 + 1 < N_NODES) ? n0 + 1 : N_NODES - 1;
    const float* h0p = H + (size_t)r0 * 128;
    const float* h1p = H + (size_t)r1 * 128;

    float a0[5] = {0, 0, 0, 0, 0};
    float a1[5] = {0, 0, 0, 0, 0};
#pragma unroll 4
    for (int k = 0; k < 128; k++) {
        float h0 = h0p[k];
        float h1 = h1p[k];
#pragma unroll
        for (int j = 0; j < 5; j++) {
            float w = Ws[k * 40 + cg * 5 + j];
            a0[j] = fmaf(h0, w, a0[j]);
            a1[j] = fmaf(h1, w, a1[j]);
        }
    }
    if (n0 < N_NODES)
#pragma unroll
        for (int j = 0; j < 5; j++) out[(size_t)n0 * 40 + cg * 5 + j] = a0[j] + bc[cg * 5 + j];
    if (n0 + 1 < N_NODES)
#pragma unroll
        for (int j = 0; j < 5; j++) out[(size_t)(n0 + 1) * 40 + cg * 5 + j] = a1[j] + bc[cg * 5 + j];
}

// ---------------- launch ----------------
extern "C" void kernel_launch(void* const* d_in, const int* in_sizes, int n_in,
                              void* d_out, int out_size) {
    const float* x   = (const float*)d_in[0];
    const int*   ei  = (const int*)d_in[1];   // int32 (JAX x64-disabled)
    const float* Wq1 = (const float*)d_in[2];  const float* bq1 = (const float*)d_in[3];
    const float* Wk1 = (const float*)d_in[4];  const float* bk1 = (const float*)d_in[5];
    const float* Wv1 = (const float*)d_in[6];  const float* bv1 = (const float*)d_in[7];
    const float* Ws1 = (const float*)d_in[8];  const float* bs1 = (const float*)d_in[9];
    const float* Wq2 = (const float*)d_in[10]; const float* bq2 = (const float*)d_in[11];
    const float* Wk2 = (const float*)d_in[12]; const float* bk2 = (const float*)d_in[13];
    const float* Wv2 = (const float*)d_in[14]; const float* bv2 = (const float*)d_in[15];
    const float* Ws2 = (const float*)d_in[16]; const float* bs2 = (const float*)d_in[17];
    const float* Wc  = (const float*)d_in[18]; const float* bc  = (const float*)d_in[19];
    float* out = (float*)d_out;

    static int configured = 0;
    if (!configured) {
        cudaFuncSetAttribute(gemm_mma_kernel<0>, cudaFuncAttributeMaxDynamicSharedMemorySize,
                             SMEM_BYTES);
        cudaFuncSetAttribute(gemm_mma_kernel<1>, cudaFuncAttributeMaxDynamicSharedMemorySize,
                             SMEM_BYTES);
        configured = 1;
    }

    // CSR build (shared by both layers)
    zero_counts_kernel<<<(N_NODES + 255) / 256, 256>>>();
    count_kernel<<<(N_EDGES + 255) / 256, 256>>>(ei);
    scan_kernel<<<1, 1024>>>();
    scatter_kernel<<<(N_EDGES + 255) / 256, 256>>>(ei);

    int nattn = N_NODES / 8;   // 12500 full blocks

    // Layer 1
    convert_w_kernel<<<(NCAT * FEAT + 255) / 256, 256>>>(Wq1, Wk1, Wv1, Ws1, bq1, bk1, bv1, bs1);
    gemm_mma_kernel<0><<<M_TILES, 256, SMEM_BYTES>>>(x);
    attn1_kernel<<<nattn, 256>>>();

    // Layer 2
    convert_w_kernel<<<(NCAT * FEAT + 255) / 256, 256>>>(Wq2, Wk2, Wv2, Ws2, bq2, bk2, bv2, bs2);
    gemm_mma_kernel<1><<<M_TILES, 256, SMEM_BYTES>>>(nullptr);
    attn2_kernel<<<nattn, 256>>>();

    // Classifier
    classifier_kernel<<<(N_NODES + 63) / 64, 256>>>(Wc, bc, out);
}

// round 14
// speedup vs baseline: 1.1219x; 1.0285x over previous
#include <cuda_runtime.h>
#include <cuda_bf16.h>
#include <cuda_fp16.h>
#include <cstdint>

#define N_NODES 100000
#define N_EDGES 1600000
#define FEAT 128
#define NCAT 512
#define M_TILES ((N_NODES + 127) / 128)
#define PAD_K 136   // bf16 elements per SMEM row (272B: 16B-aligned, conflict-free frags)

// ---------------- scratch (static __device__, no allocation) ----------------
__device__ __align__(16) float g_qsk[(size_t)N_NODES * 256];   // [node][q(128)|sk(128)] fp32, streamed
__device__ __align__(16) __half g_kvh[(size_t)N_NODES * 256];  // [node][32 x (k4|v4)] fp16, gather set (51MB)
__device__ __align__(16) float g_h1[N_NODES * FEAT];
__device__ __align__(16) float g_h2[N_NODES * FEAT];
__device__ __align__(16) __nv_bfloat16 g_wbh[2][NCAT * FEAT];  // per-layer B[n][k] = W[k][n], hi
__device__ __align__(16) __nv_bfloat16 g_wbl[2][NCAT * FEAT];  // lo
__device__ __align__(16) float g_bias[2][NCAT];
__device__ int g_counts[N_NODES];
__device__ int g_rowoff[N_NODES + 1];
__device__ int g_cursor[N_NODES];
__device__ int g_csrsrc[N_EDGES];

// ---------------- CSR build (edge_index is int32) ----------------
__global__ void zero_counts_kernel() {
    int i = blockIdx.x * blockDim.x + threadIdx.x;
    if (i < N_NODES) g_counts[i] = 0;
}
__global__ void count_kernel(const int* __restrict__ ei) {
    int e = blockIdx.x * blockDim.x + threadIdx.x;
    if (e < N_EDGES) atomicAdd(&g_counts[ei[N_EDGES + e]], 1);
}
__global__ void scan_kernel() {
    __shared__ int sums[1024];
    int tid = threadIdx.x;
    const int chunk = (N_NODES + 1023) / 1024;
    int begin = tid * chunk;
    int end = begin + chunk; if (end > N_NODES) end = N_NODES;
    int s = 0;
    for (int i = begin; i < end; i++) s += g_counts[i];
    sums[tid] = s;
    __syncthreads();
    for (int off = 1; off < 1024; off <<= 1) {
        int v = (tid >= off) ? sums[tid - off] : 0;
        __syncthreads();
        sums[tid] += v;
        __syncthreads();
    }
    int run = (tid == 0) ? 0 : sums[tid - 1];
    for (int i = begin; i < end; i++) {
        g_rowoff[i] = run;
        g_cursor[i] = run;
        run += g_counts[i];
    }
    if (tid == 1023) g_rowoff[N_NODES] = run;
}
__global__ void scatter_kernel(const int* __restrict__ ei) {
    int e = blockIdx.x * blockDim.x + threadIdx.x;
    if (e < N_EDGES) {
        int pos = atomicAdd(&g_cursor[ei[N_EDGES + e]], 1);
        g_csrsrc[pos] = ei[e];
    }
}

// ---------------- weight prep: B[n][k] = W[k][n], bf16 hi/lo + bias (per layer) ----------------
template <int LAYER>
__global__ void convert_w_kernel(const float* __restrict__ W0, const float* __restrict__ W1,
                                 const float* __restrict__ W2, const float* __restrict__ W3,
                                 const float* __restrict__ b0, const float* __restrict__ b1,
                                 const float* __restrict__ b2, const float* __restrict__ b3) {
    int i = blockIdx.x * blockDim.x + threadIdx.x;   // over 512*128
    if (i >= NCAT * FEAT) return;
    int n = i >> 7, k = i & 127;
    int widx = n >> 7, ncol = n & 127;
    const float* W = (widx == 0) ? W0 : (widx == 1) ? W1 : (widx == 2) ? W2 : W3;
    float w = W[k * 128 + ncol];
    __nv_bfloat16 h = __float2bfloat16_rn(w);
    g_wbh[LAYER][i] = h;
    g_wbl[LAYER][i] = __float2bfloat16_rn(w - __bfloat162float(h));
    if (i < NCAT) {
        const float* B = (i < 128) ? b0 : (i < 256) ? b1 : (i < 384) ? b2 : b3;
        g_bias[LAYER][i] = B[i & 127];
    }
}

// ---------------- bf16 mma.sync GEMM with A-reuse over 4 output blocks ----------------
__device__ __forceinline__ void mma16816(float c[4], uint32_t a0, uint32_t a1, uint32_t a2,
                                         uint32_t a3, uint32_t b0, uint32_t b1) {
    asm volatile(
        "mma.sync.aligned.m16n8k16.row.col.f32.bf16.bf16.f32 "
        "{%0,%1,%2,%3}, {%4,%5,%6,%7}, {%8,%9}, {%0,%1,%2,%3};"
        : "+f"(c[0]), "+f"(c[1]), "+f"(c[2]), "+f"(c[3])
        : "r"(a0), "r"(a1), "r"(a2), "r"(a3), "r"(b0), "r"(b1));
}
__device__ __forceinline__ uint32_t smem_u32(const void* p) {
    uint32_t a;
    asm("{ .reg .u64 t; cvta.to.shared.u64 t, %1; cvt.u32.u64 %0, t; }" : "=r"(a) : "l"(p));
    return a;
}
__device__ __forceinline__ void cp16(uint32_t s, const void* g) {
    asm volatile("cp.async.ca.shared.global [%0], [%1], 16;" :: "r"(s), "l"(g));
}
#define CP_COMMIT() asm volatile("cp.async.commit_group;" ::: "memory")
#define CP_WAIT(n)  asm volatile("cp.async.wait_group %0;" :: "n"(n) : "memory")

#define SM_TILE (128 * PAD_K)   // bf16 elements per tile
#define SMEM_BYTES (6 * SM_TILE * 2)   // [Ah | Al | Bh0 | Bl0 | Bh1 | Bl1]

template <int LAYER>
__device__ __forceinline__ void load_B(int nblk, int buf, uint32_t sb, int tid) {
    uint32_t bh = sb + (2 + 2 * buf) * SM_TILE * 2;
    uint32_t bl = bh + SM_TILE * 2;
    const __nv_bfloat16* gh = g_wbh[LAYER] + nblk * 128 * FEAT;
    const __nv_bfloat16* gl = g_wbl[LAYER] + nblk * 128 * FEAT;
#pragma unroll
    for (int it = 0; it < 8; it++) {
        int p = tid + 256 * it;          // 0..2047
        int row = p >> 4, k8 = p & 15;
        uint32_t so = (uint32_t)(row * PAD_K + k8 * 8) * 2;
        cp16(bh + so, gh + p * 8);
        cp16(bl + so, gl + p * 8);
    }
}

template <int SRC>
__global__ void __launch_bounds__(256, 1)
gemm_mma_kernel(const float* __restrict__ Xin) {
    extern __shared__ __nv_bfloat16 sm[];
    __nv_bfloat16* sAh = sm;
    __nv_bfloat16* sAl = sm + SM_TILE;
    uint32_t sb = smem_u32(sm);

    const float* X = (SRC == 0) ? Xin : (const float*)g_h1;
    int tid = threadIdx.x;
    int wid = tid >> 5, lane = tid & 31;
    int m0 = blockIdx.x * 128;

    load_B<SRC>(0, 0, sb, tid);
    CP_COMMIT();

    // A: load fp32, split to bf16 hi/lo in registers, stage to smem
    const float4* X4 = (const float4*)X;
#pragma unroll
    for (int it = 0; it < 16; it++) {
        int q = tid + 256 * it;          // 0..4095
        int row = q >> 5, c4 = q & 31;
        int rg = m0 + row; if (rg > N_NODES - 1) rg = N_NODES - 1;
        float4 f = X4[(size_t)rg * 32 + c4];
        __nv_bfloat16 h0 = __float2bfloat16_rn(f.x);
        __nv_bfloat16 h1 = __float2bfloat16_rn(f.y);
        __nv_bfloat16 h2 = __float2bfloat16_rn(f.z);
        __nv_bfloat16 h3 = __float2bfloat16_rn(f.w);
        __nv_bfloat16 l0 = __float2bfloat16_rn(f.x - __bfloat162float(h0));
        __nv_bfloat16 l1 = __float2bfloat16_rn(f.y - __bfloat162float(h1));
        __nv_bfloat16 l2 = __float2bfloat16_rn(f.z - __bfloat162float(h2));
        __nv_bfloat16 l3 = __float2bfloat16_rn(f.w - __bfloat162float(h3));
        __nv_bfloat162 hp0(h0, h1), hp1(h2, h3), lp0(l0, l1), lp1(l2, l3);
        uint2 hv, lv;
        hv.x = *(uint32_t*)&hp0; hv.y = *(uint32_t*)&hp1;
        lv.x = *(uint32_t*)&lp0; lv.y = *(uint32_t*)&lp1;
        int eo = row * PAD_K + c4 * 4;
        *(uint2*)&sAh[eo] = hv;
        *(uint2*)&sAl[eo] = lv;
    }

    load_B<SRC>(1, 1, sb, tid);
    CP_COMMIT();
    CP_WAIT(1);
    __syncthreads();

    int wm = wid >> 2, wn = wid & 3;
    int qid = lane >> 2, tq = (lane & 3) * 2;

    for (int nblk = 0; nblk < 4; nblk++) {
        __nv_bfloat16* sBh = sm + (2 + 2 * (nblk & 1)) * SM_TILE;
        __nv_bfloat16* sBl = sBh + SM_TILE;

        float c[4][4][4];
#pragma unroll
        for (int i = 0; i < 4; i++)
#pragma unroll
            for (int j = 0; j < 4; j++)
#pragma unroll
                for (int r = 0; r < 4; r++) c[i][j][r] = 0.f;

#pragma unroll
        for (int ks = 0; ks < 8; ks++) {
            int kb = ks * 16;
            uint32_t ah[4][4], al[4][4], bh[4][2], bl[4][2];
#pragma unroll
            for (int i = 0; i < 4; i++) {
                int r0 = (wm * 64 + i * 16 + qid) * PAD_K;
                int r8 = r0 + 8 * PAD_K;
                ah[i][0] = *(const uint32_t*)&sAh[r0 + kb + tq];
                ah[i][1] = *(const uint32_t*)&sAh[r8 + kb + tq];
                ah[i][2] = *(const uint32_t*)&sAh[r0 + kb + 8 + tq];
                ah[i][3] = *(const uint32_t*)&sAh[r8 + kb + 8 + tq];
                al[i][0] = *(const uint32_t*)&sAl[r0 + kb + tq];
                al[i][1] = *(const uint32_t*)&sAl[r8 + kb + tq];
                al[i][2] = *(const uint32_t*)&sAl[r0 + kb + 8 + tq];
                al[i][3] = *(const uint32_t*)&sAl[r8 + kb + 8 + tq];
            }
#pragma unroll
            for (int j = 0; j < 4; j++) {
                int n0 = (wn * 32 + j * 8 + qid) * PAD_K;
                bh[j][0] = *(const uint32_t*)&sBh[n0 + kb + tq];
                bh[j][1] = *(const uint32_t*)&sBh[n0 + kb + 8 + tq];
                bl[j][0] = *(const uint32_t*)&sBl[n0 + kb + tq];
                bl[j][1] = *(const uint32_t*)&sBl[n0 + kb + 8 + tq];
            }
#pragma unroll
            for (int i = 0; i < 4; i++)
#pragma unroll
                for (int j = 0; j < 4; j++) {
                    mma16816(c[i][j], ah[i][0], ah[i][1], ah[i][2], ah[i][3], bh[j][0], bh[j][1]);
                    mma16816(c[i][j], al[i][0], al[i][1], al[i][2], al[i][3], bh[j][0], bh[j][1]);
                    mma16816(c[i][j], ah[i][0], ah[i][1], ah[i][2], ah[i][3], bl[j][0], bl[j][1]);
                }
        }

        // epilogue routing:
        //   q (0), sk (3) -> fp32 g_qsk at col offset 0 / 128
        //   k (1), v (2)  -> fp16 g_kvh interleaved: elem = row*256 + (c>>2)*8 + sel*4 + (c&3)
        bool is_qsk = (nblk == 0 || nblk == 3);
        int colofs = (nblk == 3) ? 128 : 0;
        int sel = (nblk == 2) ? 1 : 0;
#pragma unroll
        for (int i = 0; i < 4; i++) {
            int row = m0 + wm * 64 + i * 16 + qid;
#pragma unroll
            for (int j = 0; j < 4; j++) {
                int col = wn * 32 + j * 8 + tq;   // even, pair (col, col+1) in same 4-chunk
                float2 bb = *(const float2*)&g_bias[SRC][nblk * 128 + col];
                float2 o0 = {c[i][j][0] + bb.x, c[i][j][1] + bb.y};
                float2 o1 = {c[i][j][2] + bb.x, c[i][j][3] + bb.y};
                if (is_qsk) {
                    if (row < N_NODES)
                        *(float2*)&g_qsk[(size_t)row * 256 + colofs + col] = o0;
                    if (row + 8 < N_NODES)
                        *(float2*)&g_qsk[(size_t)(row + 8) * 256 + colofs + col] = o1;
                } else {
                    uint32_t eo = (uint32_t)((col >> 2) * 8 + sel * 4 + (col & 3));
                    if (row < N_NODES) {
                        __half2 p = __floats2half2_rn(o0.x, o0.y);
                        *(__half2*)&g_kvh[(size_t)row * 256 + eo] = p;
                    }
                    if (row + 8 < N_NODES) {
                        __half2 p = __floats2half2_rn(o1.x, o1.y);
                        *(__half2*)&g_kvh[(size_t)(row + 8) * 256 + eo] = p;
                    }
                }
            }
        }

        if (nblk < 3) {
            __syncthreads();
            if (nblk + 2 <= 3) {
                load_B<SRC>(nblk + 2, nblk & 1, sb, tid);
                CP_COMMIT();
                CP_WAIT(1);
            } else {
                CP_WAIT(0);
            }
            __syncthreads();
        }
    }
}

// ---------------- attention core: one LDG.128/edge (fp16 k4|v4), 2-edge pipeline ----------------
__device__ __forceinline__ float4 attn_node(int node, int lane) {
    const float4* qsk = (const float4*)g_qsk;        // 64 float4 per row
    const uint4*  kvh = (const uint4*)g_kvh;         // 32 uint4 per row: [k4(fp16)|v4(fp16)]

    float4 qv = qsk[(size_t)node * 64 + lane];
    qv.x *= 0.125f; qv.y *= 0.125f; qv.z *= 0.125f; qv.w *= 0.125f;  // 1/sqrt(64)

    int e0 = g_rowoff[node];
    int e1 = g_rowoff[node + 1];

    float sA = 0.f, sB = 0.f;
    float4 aA = {0.f, 0.f, 0.f, 0.f}, aB = {0.f, 0.f, 0.f, 0.f};

    int e = e0;
    for (; e + 2 <= e1; e += 2) {
        int s0 = g_csrsrc[e];
        int s1 = g_csrsrc[e + 1];
        uint4 c0 = kvh[(size_t)s0 * 32 + lane];
        uint4 c1 = kvh[(size_t)s1 * 32 + lane];
        float2 k0a = __half22float2(*(__half2*)&c0.x);
        float2 k0b = __half22float2(*(__half2*)&c0.y);
        float2 v0a = __half22float2(*(__half2*)&c0.z);
        float2 v0b = __half22float2(*(__half2*)&c0.w);
        float2 k1a = __half22float2(*(__half2*)&c1.x);
        float2 k1b = __half22float2(*(__half2*)&c1.y);
        float2 v1a = __half22float2(*(__half2*)&c1.z);
        float2 v1b = __half22float2(*(__half2*)&c1.w);
        float d0 = fmaf(qv.x, k0a.x, fmaf(qv.y, k0a.y, fmaf(qv.z, k0b.x, qv.w * k0b.y)));
        float d1 = fmaf(qv.x, k1a.x, fmaf(qv.y, k1a.y, fmaf(qv.z, k1b.x, qv.w * k1b.y)));
        d0 += __shfl_xor_sync(0xffffffffu, d0, 8);
        d1 += __shfl_xor_sync(0xffffffffu, d1, 8);
        d0 += __shfl_xor_sync(0xffffffffu, d0, 4);
        d1 += __shfl_xor_sync(0xffffffffu, d1, 4);
        d0 += __shfl_xor_sync(0xffffffffu, d0, 2);
        d1 += __shfl_xor_sync(0xffffffffu, d1, 2);
        d0 += __shfl_xor_sync(0xffffffffu, d0, 1);
        d1 += __shfl_xor_sync(0xffffffffu, d1, 1);
        float w0 = __expf(d0);
        float w1 = __expf(d1);
        sA += w0; sB += w1;
        aA.x = fmaf(w0, v0a.x, aA.x); aB.x = fmaf(w1, v1a.x, aB.x);
        aA.y = fmaf(w0, v0a.y, aA.y); aB.y = fmaf(w1, v1a.y, aB.y);
        aA.z = fmaf(w0, v0b.x, aA.z); aB.z = fmaf(w1, v1b.x, aB.z);
        aA.w = fmaf(w0, v0b.y, aA.w); aB.w = fmaf(w1, v1b.y, aB.w);
    }
    if (e < e1) {
        int s0 = g_csrsrc[e];
        uint4 c0 = kvh[(size_t)s0 * 32 + lane];
        float2 k0a = __half22float2(*(__half2*)&c0.x);
        float2 k0b = __half22float2(*(__half2*)&c0.y);
        float2 v0a = __half22float2(*(__half2*)&c0.z);
        float2 v0b = __half22float2(*(__half2*)&c0.w);
        float d0 = fmaf(qv.x, k0a.x, fmaf(qv.y, k0a.y, fmaf(qv.z, k0b.x, qv.w * k0b.y)));
        d0 += __shfl_xor_sync(0xffffffffu, d0, 8);
        d0 += __shfl_xor_sync(0xffffffffu, d0, 4);
        d0 += __shfl_xor_sync(0xffffffffu, d0, 2);
        d0 += __shfl_xor_sync(0xffffffffu, d0, 1);
        float w0 = __expf(d0);
        sA += w0;
        aA.x = fmaf(w0, v0a.x, aA.x);
        aA.y = fmaf(w0, v0a.y, aA.y);
        aA.z = fmaf(w0, v0b.x, aA.z);
        aA.w = fmaf(w0, v0b.y, aA.w);
    }

    float s = sA + sB;
    float inv = 1.0f / fmaxf(s, 1e-16f);
    float4 sk = qsk[(size_t)node * 64 + 32 + lane];
    float4 o;
    o.x = fmaf(aA.x + aB.x, inv, sk.x);
    o.y = fmaf(aA.y + aB.y, inv, sk.y);
    o.z = fmaf(aA.z + aB.z, inv, sk.z);
    o.w = fmaf(aA.w + aB.w, inv, sk.w);
    return o;
}

// Layer 1: attn + ELU -> g_h1 (fp32; layer-2 GEMM converts inline)
__global__ void attn1_kernel() {
    int node = blockIdx.x * 8 + (threadIdx.x >> 5);   // N_NODES % 8 == 0
    int lane = threadIdx.x & 31;
    float4 o = attn_node(node, lane);
    o.x = (o.x > 0.f) ? o.x : expm1f(o.x);
    o.y = (o.y > 0.f) ? o.y : expm1f(o.y);
    o.z = (o.z > 0.f) ? o.z : expm1f(o.z);
    o.w = (o.w > 0.f) ? o.w : expm1f(o.w);
    ((float4*)g_h1)[(size_t)node * 32 + lane] = o;
}

// Layer 2: attn -> g_h2
__global__ void attn2_kernel() {
    int node = blockIdx.x * 8 + (threadIdx.x >> 5);
    int lane = threadIdx.x & 31;
    float4 o = attn_node(node, lane);
    ((float4*)g_h2)[(size_t)node * 32 + lane] = o;
}

// ---------------- classifier: out = g_h2 @ Wc + bc  (128 -> 40) ----------------
__global__ void classifier_kernel(const float* __restrict__ Wc,
                                  const float* __restrict__ bc,
                                  float* __restrict__ out) {
    const float* H = (const float*)g_h2;
    __shared__ float Ws[128 * 40];
    for (int i = threadIdx.x; i < 128 * 40; i += 256) Ws[i] = Wc[i];
    __syncthreads();

    int cg = threadIdx.x & 7;
    int nr = threadIdx.x >> 3;
    int n0 = blockIdx.x * 64 + nr * 2;

    int r0 = (n0     < N_NODES) ? n0     : N_NODES - 1;
    int r1 = (n0 + 1 < N_NODES) ? n0 + 1 : N_NODES - 1;
    const float* h0p = H + (size_t)r0 * 128;
    const float* h1p = H + (size_t)r1 * 128;

    float a0[5] = {0, 0, 0, 0, 0};
    float a1[5] = {0, 0, 0, 0, 0};
#pragma unroll 4
    for (int k = 0; k < 128; k++) {
        float h0 = h0p[k];
        float h1 = h1p[k];
#pragma unroll
        for (int j = 0; j < 5; j++) {
            float w = Ws[k * 40 + cg * 5 + j];
            a0[j] = fmaf(h0, w, a0[j]);
            a1[j] = fmaf(h1, w, a1[j]);
        }
    }
    if (n0 < N_NODES)
#pragma unroll
        for (int j = 0; j < 5; j++) out[(size_t)n0 * 40 + cg * 5 + j] = a0[j] + bc[cg * 5 + j];
    if (n0 + 1 < N_NODES)
#pragma unroll
        for (int j = 0; j < 5; j++) out[(size_t)(n0 + 1) * 40 + cg * 5 + j] = a1[j] + bc[cg * 5 + j];
}

// ---------------- launch ----------------
extern "C" void kernel_launch(void* const* d_in, const int* in_sizes, int n_in,
                              void* d_out, int out_size) {
    const float* x   = (const float*)d_in[0];
    const int*   ei  = (const int*)d_in[1];   // int32 (JAX x64-disabled)
    const float* Wq1 = (const float*)d_in[2];  const float* bq1 = (const float*)d_in[3];
    const float* Wk1 = (const float*)d_in[4];  const float* bk1 = (const float*)d_in[5];
    const float* Wv1 = (const float*)d_in[6];  const float* bv1 = (const float*)d_in[7];
    const float* Ws1 = (const float*)d_in[8];  const float* bs1 = (const float*)d_in[9];
    const float* Wq2 = (const float*)d_in[10]; const float* bq2 = (const float*)d_in[11];
    const float* Wk2 = (const float*)d_in[12]; const float* bk2 = (const float*)d_in[13];
    const float* Wv2 = (const float*)d_in[14]; const float* bv2 = (const float*)d_in[15];
    const float* Ws2 = (const float*)d_in[16]; const float* bs2 = (const float*)d_in[17];
    const float* Wc  = (const float*)d_in[18]; const float* bc  = (const float*)d_in[19];
    float* out = (float*)d_out;

    static int configured = 0;
    static cudaStream_t s2;
    static cudaEvent_t evFork, evJoin;
    if (!configured) {
        cudaFuncSetAttribute(gemm_mma_kernel<0>, cudaFuncAttributeMaxDynamicSharedMemorySize,
                             SMEM_BYTES);
        cudaFuncSetAttribute(gemm_mma_kernel<1>, cudaFuncAttributeMaxDynamicSharedMemorySize,
                             SMEM_BYTES);
        cudaStreamCreateWithFlags(&s2, cudaStreamNonBlocking);
        cudaEventCreateWithFlags(&evFork, cudaEventDisableTiming);
        cudaEventCreateWithFlags(&evJoin, cudaEventDisableTiming);
        configured = 1;
    }

    int nattn = N_NODES / 8;   // 12500 full blocks

    // ---- fork: CSR build + layer-2 weight conversion on side stream ----
    cudaEventRecord(evFork, 0);
    cudaStreamWaitEvent(s2, evFork, 0);
    zero_counts_kernel<<<(N_NODES + 255) / 256, 256, 0, s2>>>();
    count_kernel<<<(N_EDGES + 255) / 256, 256, 0, s2>>>(ei);
    scan_kernel<<<1, 1024, 0, s2>>>();
    scatter_kernel<<<(N_EDGES + 255) / 256, 256, 0, s2>>>(ei);
    convert_w_kernel<1><<<(NCAT * FEAT + 255) / 256, 256, 0, s2>>>(Wq2, Wk2, Wv2, Ws2,
                                                                   bq2, bk2, bv2, bs2);
    cudaEventRecord(evJoin, s2);

    // ---- main stream: layer-1 weight conversion + GEMM (parallel with CSR) ----
    convert_w_kernel<0><<<(NCAT * FEAT + 255) / 256, 256>>>(Wq1, Wk1, Wv1, Ws1,
                                                            bq1, bk1, bv1, bs1);
    gemm_mma_kernel<0><<<M_TILES, 256, SMEM_BYTES>>>(x);

    // ---- join: attn1 needs CSR + gemm1 ----
    cudaStreamWaitEvent(0, evJoin, 0);
    attn1_kernel<<<nattn, 256>>>();

    // Layer 2 (weights already converted on side stream)
    gemm_mma_kernel<1><<<M_TILES, 256, SMEM_BYTES>>>(nullptr);
    attn2_kernel<<<nattn, 256>>>();

    // Classifier
    classifier_kernel<<<(N_NODES + 63) / 64, 256>>>(Wc, bc, out);
}

// round 15
// speedup vs baseline: 1.2853x; 1.1456x over previous
#include <cuda_runtime.h>
#include <cuda_fp16.h>
#include <cstdint>

#define N_NODES 100000
#define N_EDGES 1600000
#define FEAT 128
#define NCAT 512
#define M_TILES ((N_NODES + 127) / 128)
#define PAD_K 136   // fp16 elements per SMEM row (272B: 16B-aligned, conflict-free frags)

// ---------------- scratch (static __device__, no allocation) ----------------
__device__ __align__(16) float g_qsk[(size_t)N_NODES * 256];   // [node][q(128)|sk(128)] fp32, streamed
__device__ __align__(16) __half g_kvh[(size_t)N_NODES * 256];  // [node][32 x (k4|v4)] fp16, gather set (51MB)
__device__ __align__(16) float g_h1[N_NODES * FEAT];
__device__ __align__(16) float g_h2[N_NODES * FEAT];
__device__ __align__(16) __half g_wbh[2][NCAT * FEAT];  // per-layer B[n][k] = W[k][n], fp16 hi
__device__ __align__(16) __half g_wbl[2][NCAT * FEAT];  // fp16 lo
__device__ __align__(16) float g_bias[2][NCAT];
__device__ int g_counts[N_NODES];
__device__ int g_rowoff[N_NODES + 1];
__device__ int g_cursor[N_NODES];
__device__ int g_csrsrc[N_EDGES];

// ---------------- CSR build (edge_index is int32) ----------------
__global__ void zero_counts_kernel() {
    int i = blockIdx.x * blockDim.x + threadIdx.x;
    if (i < N_NODES) g_counts[i] = 0;
}
__global__ void count_kernel(const int* __restrict__ ei) {
    int e = blockIdx.x * blockDim.x + threadIdx.x;
    if (e < N_EDGES) atomicAdd(&g_counts[ei[N_EDGES + e]], 1);
}
__global__ void scan_kernel() {
    __shared__ int sums[1024];
    int tid = threadIdx.x;
    const int chunk = (N_NODES + 1023) / 1024;
    int begin = tid * chunk;
    int end = begin + chunk; if (end > N_NODES) end = N_NODES;
    int s = 0;
    for (int i = begin; i < end; i++) s += g_counts[i];
    sums[tid] = s;
    __syncthreads();
    for (int off = 1; off < 1024; off <<= 1) {
        int v = (tid >= off) ? sums[tid - off] : 0;
        __syncthreads();
        sums[tid] += v;
        __syncthreads();
    }
    int run = (tid == 0) ? 0 : sums[tid - 1];
    for (int i = begin; i < end; i++) {
        g_rowoff[i] = run;
        g_cursor[i] = run;
        run += g_counts[i];
    }
    if (tid == 1023) g_rowoff[N_NODES] = run;
}
__global__ void scatter_kernel(const int* __restrict__ ei) {
    int e = blockIdx.x * blockDim.x + threadIdx.x;
    if (e < N_EDGES) {
        int pos = atomicAdd(&g_cursor[ei[N_EDGES + e]], 1);
        g_csrsrc[pos] = ei[e];
    }
}

// ---------------- weight prep: B[n][k] = W[k][n], fp16 hi/lo + bias (per layer) ----------------
template <int LAYER>
__global__ void convert_w_kernel(const float* __restrict__ W0, const float* __restrict__ W1,
                                 const float* __restrict__ W2, const float* __restrict__ W3,
                                 const float* __restrict__ b0, const float* __restrict__ b1,
                                 const float* __restrict__ b2, const float* __restrict__ b3) {
    int i = blockIdx.x * blockDim.x + threadIdx.x;   // over 512*128
    if (i >= NCAT * FEAT) return;
    int n = i >> 7, k = i & 127;
    int widx = n >> 7, ncol = n & 127;
    const float* W = (widx == 0) ? W0 : (widx == 1) ? W1 : (widx == 2) ? W2 : W3;
    float w = W[k * 128 + ncol];
    __half h = __float2half_rn(w);
    g_wbh[LAYER][i] = h;
    g_wbl[LAYER][i] = __float2half_rn(w - __half2float(h));
    if (i < NCAT) {
        const float* B = (i < 128) ? b0 : (i < 256) ? b1 : (i < 384) ? b2 : b3;
        g_bias[LAYER][i] = B[i & 127];
    }
}

// ---------------- fp16 mma.sync GEMM with A-reuse over 4 output blocks ----------------
// Terms per block: q/k/v = 2 (Ah*Bh + Al*Bh; A exact, B fp16-quantized), skip = 3 (adds Ah*Bl).
__device__ __forceinline__ void mma16816(float c[4], uint32_t a0, uint32_t a1, uint32_t a2,
                                         uint32_t a3, uint32_t b0, uint32_t b1) {
    asm volatile(
        "mma.sync.aligned.m16n8k16.row.col.f32.f16.f16.f32 "
        "{%0,%1,%2,%3}, {%4,%5,%6,%7}, {%8,%9}, {%0,%1,%2,%3};"
        : "+f"(c[0]), "+f"(c[1]), "+f"(c[2]), "+f"(c[3])
        : "r"(a0), "r"(a1), "r"(a2), "r"(a3), "r"(b0), "r"(b1));
}
__device__ __forceinline__ uint32_t smem_u32(const void* p) {
    uint32_t a;
    asm("{ .reg .u64 t; cvta.to.shared.u64 t, %1; cvt.u32.u64 %0, t; }" : "=r"(a) : "l"(p));
    return a;
}
__device__ __forceinline__ void cp16(uint32_t s, const void* g) {
    asm volatile("cp.async.ca.shared.global [%0], [%1], 16;" :: "r"(s), "l"(g));
}
#define CP_COMMIT() asm volatile("cp.async.commit_group;" ::: "memory")
#define CP_WAIT(n)  asm volatile("cp.async.wait_group %0;" :: "n"(n) : "memory")

#define SM_TILE (128 * PAD_K)   // fp16 elements per tile
#define SMEM_BYTES (6 * SM_TILE * 2)   // [Ah | Al | Bh0 | Bl0 | Bh1 | Bl1]

template <int LAYER>
__device__ __forceinline__ void load_B(int nblk, int buf, uint32_t sb, int tid) {
    uint32_t bh = sb + (2 + 2 * buf) * SM_TILE * 2;
    uint32_t bl = bh + SM_TILE * 2;
    const __half* gh = g_wbh[LAYER] + nblk * 128 * FEAT;
    const __half* gl = g_wbl[LAYER] + nblk * 128 * FEAT;
#pragma unroll
    for (int it = 0; it < 8; it++) {
        int p = tid + 256 * it;          // 0..2047
        int row = p >> 4, k8 = p & 15;
        uint32_t so = (uint32_t)(row * PAD_K + k8 * 8) * 2;
        cp16(bh + so, gh + p * 8);
        cp16(bl + so, gl + p * 8);
    }
}

template <int SRC>
__global__ void __launch_bounds__(256, 1)
gemm_mma_kernel(const float* __restrict__ Xin) {
    extern __shared__ __half sm[];
    __half* sAh = sm;
    __half* sAl = sm + SM_TILE;
    uint32_t sb = smem_u32(sm);

    const float* X = (SRC == 0) ? Xin : (const float*)g_h1;
    int tid = threadIdx.x;
    int wid = tid >> 5, lane = tid & 31;
    int m0 = blockIdx.x * 128;

    load_B<SRC>(0, 0, sb, tid);
    CP_COMMIT();

    // A: load fp32 (streaming), split to fp16 hi/lo in registers, stage to smem
    const float4* X4 = (const float4*)X;
#pragma unroll
    for (int it = 0; it < 16; it++) {
        int q = tid + 256 * it;          // 0..4095
        int row = q >> 5, c4 = q & 31;
        int rg = m0 + row; if (rg > N_NODES - 1) rg = N_NODES - 1;
        float4 f = __ldcs(X4 + (size_t)rg * 32 + c4);
        __half h0 = __float2half_rn(f.x);
        __half h1 = __float2half_rn(f.y);
        __half h2 = __float2half_rn(f.z);
        __half h3 = __float2half_rn(f.w);
        __half l0 = __float2half_rn(f.x - __half2float(h0));
        __half l1 = __float2half_rn(f.y - __half2float(h1));
        __half l2 = __float2half_rn(f.z - __half2float(h2));
        __half l3 = __float2half_rn(f.w - __half2float(h3));
        __half2 hp0(h0, h1), hp1(h2, h3), lp0(l0, l1), lp1(l2, l3);
        uint2 hv, lv;
        hv.x = *(uint32_t*)&hp0; hv.y = *(uint32_t*)&hp1;
        lv.x = *(uint32_t*)&lp0; lv.y = *(uint32_t*)&lp1;
        int eo = row * PAD_K + c4 * 4;
        *(uint2*)&sAh[eo] = hv;
        *(uint2*)&sAl[eo] = lv;
    }

    load_B<SRC>(1, 1, sb, tid);
    CP_COMMIT();
    CP_WAIT(1);
    __syncthreads();

    int wm = wid >> 2, wn = wid & 3;
    int qid = lane >> 2, tq = (lane & 3) * 2;

    for (int nblk = 0; nblk < 4; nblk++) {
        __half* sBh = sm + (2 + 2 * (nblk & 1)) * SM_TILE;
        __half* sBl = sBh + SM_TILE;
        bool third = (nblk == 3);   // skip path: full 3-term accuracy

        float c[4][4][4];
#pragma unroll
        for (int i = 0; i < 4; i++)
#pragma unroll
            for (int j = 0; j < 4; j++)
#pragma unroll
                for (int r = 0; r < 4; r++) c[i][j][r] = 0.f;

#pragma unroll
        for (int ks = 0; ks < 8; ks++) {
            int kb = ks * 16;
            uint32_t ah[4][4], al[4][4], bh[4][2], bl[4][2];
#pragma unroll
            for (int i = 0; i < 4; i++) {
                int r0 = (wm * 64 + i * 16 + qid) * PAD_K;
                int r8 = r0 + 8 * PAD_K;
                ah[i][0] = *(const uint32_t*)&sAh[r0 + kb + tq];
                ah[i][1] = *(const uint32_t*)&sAh[r8 + kb + tq];
                ah[i][2] = *(const uint32_t*)&sAh[r0 + kb + 8 + tq];
                ah[i][3] = *(const uint32_t*)&sAh[r8 + kb + 8 + tq];
                al[i][0] = *(const uint32_t*)&sAl[r0 + kb + tq];
                al[i][1] = *(const uint32_t*)&sAl[r8 + kb + tq];
                al[i][2] = *(const uint32_t*)&sAl[r0 + kb + 8 + tq];
                al[i][3] = *(const uint32_t*)&sAl[r8 + kb + 8 + tq];
            }
#pragma unroll
            for (int j = 0; j < 4; j++) {
                int n0 = (wn * 32 + j * 8 + qid) * PAD_K;
                bh[j][0] = *(const uint32_t*)&sBh[n0 + kb + tq];
                bh[j][1] = *(const uint32_t*)&sBh[n0 + kb + 8 + tq];
                if (third) {
                    bl[j][0] = *(const uint32_t*)&sBl[n0 + kb + tq];
                    bl[j][1] = *(const uint32_t*)&sBl[n0 + kb + 8 + tq];
                }
            }
#pragma unroll
            for (int i = 0; i < 4; i++)
#pragma unroll
                for (int j = 0; j < 4; j++) {
                    mma16816(c[i][j], ah[i][0], ah[i][1], ah[i][2], ah[i][3], bh[j][0], bh[j][1]);
                    mma16816(c[i][j], al[i][0], al[i][1], al[i][2], al[i][3], bh[j][0], bh[j][1]);
                    if (third)
                        mma16816(c[i][j], ah[i][0], ah[i][1], ah[i][2], ah[i][3], bl[j][0], bl[j][1]);
                }
        }

        // epilogue routing:
        //   q (0), sk (3) -> fp32 g_qsk (streaming store) at col offset 0 / 128
        //   k (1), v (2)  -> fp16 g_kvh interleaved (default store: keep L2-resident)
        bool is_qsk = (nblk == 0 || nblk == 3);
        int colofs = (nblk == 3) ? 128 : 0;
        int sel = (nblk == 2) ? 1 : 0;
#pragma unroll
        for (int i = 0; i < 4; i++) {
            int row = m0 + wm * 64 + i * 16 + qid;
#pragma unroll
            for (int j = 0; j < 4; j++) {
                int col = wn * 32 + j * 8 + tq;   // even, pair (col, col+1) in same 4-chunk
                float2 bb = *(const float2*)&g_bias[SRC][nblk * 128 + col];
                float2 o0 = {c[i][j][0] + bb.x, c[i][j][1] + bb.y};
                float2 o1 = {c[i][j][2] + bb.x, c[i][j][3] + bb.y};
                if (is_qsk) {
                    if (row < N_NODES)
                        __stcs((float2*)&g_qsk[(size_t)row * 256 + colofs + col], o0);
                    if (row + 8 < N_NODES)
                        __stcs((float2*)&g_qsk[(size_t)(row + 8) * 256 + colofs + col], o1);
                } else {
                    uint32_t eo = (uint32_t)((col >> 2) * 8 + sel * 4 + (col & 3));
                    if (row < N_NODES) {
                        __half2 p = __floats2half2_rn(o0.x, o0.y);
                        *(__half2*)&g_kvh[(size_t)row * 256 + eo] = p;
                    }
                    if (row + 8 < N_NODES) {
                        __half2 p = __floats2half2_rn(o1.x, o1.y);
                        *(__half2*)&g_kvh[(size_t)(row + 8) * 256 + eo] = p;
                    }
                }
            }
        }

        if (nblk < 3) {
            __syncthreads();
            if (nblk + 2 <= 3) {
                load_B<SRC>(nblk + 2, nblk & 1, sb, tid);
                CP_COMMIT();
                CP_WAIT(1);
            } else {
                CP_WAIT(0);
            }
            __syncthreads();
        }
    }
}

// ---------------- attention core: one LDG.128/edge (fp16 k4|v4), 2-edge pipeline ----------------
// q/sk: __ldcs (read-once streaming) so the 51MB kv gather set keeps L2 residency.
__device__ __forceinline__ float4 attn_node(int node, int lane) {
    const float4* qsk = (const float4*)g_qsk;        // 64 float4 per row
    const uint4*  kvh = (const uint4*)g_kvh;         // 32 uint4 per row: [k4(fp16)|v4(fp16)]

    float4 qv = __ldcs(qsk + (size_t)node * 64 + lane);
    qv.x *= 0.125f; qv.y *= 0.125f; qv.z *= 0.125f; qv.w *= 0.125f;  // 1/sqrt(64)

    int e0 = g_rowoff[node];
    int e1 = g_rowoff[node + 1];

    float sA = 0.f, sB = 0.f;
    float4 aA = {0.f, 0.f, 0.f, 0.f}, aB = {0.f, 0.f, 0.f, 0.f};

    int e = e0;
    for (; e + 2 <= e1; e += 2) {
        int s0 = g_csrsrc[e];
        int s1 = g_csrsrc[e + 1];
        uint4 c0 = kvh[(size_t)s0 * 32 + lane];
        uint4 c1 = kvh[(size_t)s1 * 32 + lane];
        float2 k0a = __half22float2(*(__half2*)&c0.x);
        float2 k0b = __half22float2(*(__half2*)&c0.y);
        float2 v0a = __half22float2(*(__half2*)&c0.z);
        float2 v0b = __half22float2(*(__half2*)&c0.w);
        float2 k1a = __half22float2(*(__half2*)&c1.x);
        float2 k1b = __half22float2(*(__half2*)&c1.y);
        float2 v1a = __half22float2(*(__half2*)&c1.z);
        float2 v1b = __half22float2(*(__half2*)&c1.w);
        float d0 = fmaf(qv.x, k0a.x, fmaf(qv.y, k0a.y, fmaf(qv.z, k0b.x, qv.w * k0b.y)));
        float d1 = fmaf(qv.x, k1a.x, fmaf(qv.y, k1a.y, fmaf(qv.z, k1b.x, qv.w * k1b.y)));
        d0 += __shfl_xor_sync(0xffffffffu, d0, 8);
        d1 += __shfl_xor_sync(0xffffffffu, d1, 8);
        d0 += __shfl_xor_sync(0xffffffffu, d0, 4);
        d1 += __shfl_xor_sync(0xffffffffu, d1, 4);
        d0 += __shfl_xor_sync(0xffffffffu, d0, 2);
        d1 += __shfl_xor_sync(0xffffffffu, d1, 2);
        d0 += __shfl_xor_sync(0xffffffffu, d0, 1);
        d1 += __shfl_xor_sync(0xffffffffu, d1, 1);
        float w0 = __expf(d0);
        float w1 = __expf(d1);
        sA += w0; sB += w1;
        aA.x = fmaf(w0, v0a.x, aA.x); aB.x = fmaf(w1, v1a.x, aB.x);
        aA.y = fmaf(w0, v0a.y, aA.y); aB.y = fmaf(w1, v1a.y, aB.y);
        aA.z = fmaf(w0, v0b.x, aA.z); aB.z = fmaf(w1, v1b.x, aB.z);
        aA.w = fmaf(w0, v0b.y, aA.w); aB.w = fmaf(w1, v1b.y, aB.w);
    }
    if (e < e1) {
        int s0 = g_csrsrc[e];
        uint4 c0 = kvh[(size_t)s0 * 32 + lane];
        float2 k0a = __half22float2(*(__half2*)&c0.x);
        float2 k0b = __half22float2(*(__half2*)&c0.y);
        float2 v0a = __half22float2(*(__half2*)&c0.z);
        float2 v0b = __half22float2(*(__half2*)&c0.w);
        float d0 = fmaf(qv.x, k0a.x, fmaf(qv.y, k0a.y, fmaf(qv.z, k0b.x, qv.w * k0b.y)));
        d0 += __shfl_xor_sync(0xffffffffu, d0, 8);
        d0 += __shfl_xor_sync(0xffffffffu, d0, 4);
        d0 += __shfl_xor_sync(0xffffffffu, d0, 2);
        d0 += __shfl_xor_sync(0xffffffffu, d0, 1);
        float w0 = __expf(d0);
        sA += w0;
        aA.x = fmaf(w0, v0a.x, aA.x);
        aA.y = fmaf(w0, v0a.y, aA.y);
        aA.z = fmaf(w0, v0b.x, aA.z);
        aA.w = fmaf(w0, v0b.y, aA.w);
    }

    float s = sA + sB;
    float inv = 1.0f / fmaxf(s, 1e-16f);
    float4 sk = __ldcs(qsk + (size_t)node * 64 + 32 + lane);
    float4 o;
    o.x = fmaf(aA.x + aB.x, inv, sk.x);
    o.y = fmaf(aA.y + aB.y, inv, sk.y);
    o.z = fmaf(aA.z + aB.z, inv, sk.z);
    o.w = fmaf(aA.w + aB.w, inv, sk.w);
    return o;
}

// Layer 1: attn + ELU -> g_h1 (fp32, streaming store; layer-2 GEMM converts inline)
__global__ void attn1_kernel() {
    int node = blockIdx.x * 8 + (threadIdx.x >> 5);   // N_NODES % 8 == 0
    int lane = threadIdx.x & 31;
    float4 o = attn_node(node, lane);
    o.x = (o.x > 0.f) ? o.x : expm1f(o.x);
    o.y = (o.y > 0.f) ? o.y : expm1f(o.y);
    o.z = (o.z > 0.f) ? o.z : expm1f(o.z);
    o.w = (o.w > 0.f) ? o.w : expm1f(o.w);
    __stcs((float4*)g_h1 + (size_t)node * 32 + lane, o);
}

// Layer 2: attn -> g_h2 (streaming store)
__global__ void attn2_kernel() {
    int node = blockIdx.x * 8 + (threadIdx.x >> 5);
    int lane = threadIdx.x & 31;
    float4 o = attn_node(node, lane);
    __stcs((float4*)g_h2 + (size_t)node * 32 + lane, o);
}

// ---------------- classifier: out = g_h2 @ Wc + bc  (128 -> 40) ----------------
__global__ void classifier_kernel(const float* __restrict__ Wc,
                                  const float* __restrict__ bc,
                                  float* __restrict__ out) {
    const float* H = (const float*)g_h2;
    __shared__ float Ws[128 * 40];
    for (int i = threadIdx.x; i < 128 * 40; i += 256) Ws[i] = Wc[i];
    __syncthreads();

    int cg = threadIdx.x & 7;
    int nr = threadIdx.x >> 3;
    int n0 = blockIdx.x * 64 + nr * 2;

    int r0 = (n0     < N_NODES) ? n0     : N_NODES - 1;
    int r1 = (n0 + 1 < N_NODES) ? n0 + 1 : N_NODES - 1;
    const float* h0p = H + (size_t)r0 * 128;
    const float* h1p = H + (size_t)r1 * 128;

    float a0[5] = {0, 0, 0, 0, 0};
    float a1[5] = {0, 0, 0, 0, 0};
#pragma unroll 4
    for (int k = 0; k < 128; k++) {
        float h0 = __ldcs(h0p + k);
        float h1 = __ldcs(h1p + k);
#pragma unroll
        for (int j = 0; j < 5; j++) {
            float w = Ws[k * 40 + cg * 5 + j];
            a0[j] = fmaf(h0, w, a0[j]);
            a1[j] = fmaf(h1, w, a1[j]);
        }
    }
    if (n0 < N_NODES)
#pragma unroll
        for (int j = 0; j < 5; j++) out[(size_t)n0 * 40 + cg * 5 + j] = a0[j] + bc[cg * 5 + j];
    if (n0 + 1 < N_NODES)
#pragma unroll
        for (int j = 0; j < 5; j++) out[(size_t)(n0 + 1) * 40 + cg * 5 + j] = a1[j] + bc[cg * 5 + j];
}

// ---------------- launch ----------------
extern "C" void kernel_launch(void* const* d_in, const int* in_sizes, int n_in,
                              void* d_out, int out_size) {
    const float* x   = (const float*)d_in[0];
    const int*   ei  = (const int*)d_in[1];   // int32 (JAX x64-disabled)
    const float* Wq1 = (const float*)d_in[2];  const float* bq1 = (const float*)d_in[3];
    const float* Wk1 = (const float*)d_in[4];  const float* bk1 = (const float*)d_in[5];
    const float* Wv1 = (const float*)d_in[6];  const float* bv1 = (const float*)d_in[7];
    const float* Ws1 = (const float*)d_in[8];  const float* bs1 = (const float*)d_in[9];
    const float* Wq2 = (const float*)d_in[10]; const float* bq2 = (const float*)d_in[11];
    const float* Wk2 = (const float*)d_in[12]; const float* bk2 = (const float*)d_in[13];
    const float* Wv2 = (const float*)d_in[14]; const float* bv2 = (const float*)d_in[15];
    const float* Ws2 = (const float*)d_in[16]; const float* bs2 = (const float*)d_in[17];
    const float* Wc  = (const float*)d_in[18]; const float* bc  = (const float*)d_in[19];
    float* out = (float*)d_out;

    static int configured = 0;
    static cudaStream_t s2;
    static cudaEvent_t evFork, evJoin;
    if (!configured) {
        cudaFuncSetAttribute(gemm_mma_kernel<0>, cudaFuncAttributeMaxDynamicSharedMemorySize,
                             SMEM_BYTES);
        cudaFuncSetAttribute(gemm_mma_kernel<1>, cudaFuncAttributeMaxDynamicSharedMemorySize,
                             SMEM_BYTES);
        cudaStreamCreateWithFlags(&s2, cudaStreamNonBlocking);
        cudaEventCreateWithFlags(&evFork, cudaEventDisableTiming);
        cudaEventCreateWithFlags(&evJoin, cudaEventDisableTiming);
        configured = 1;
    }

    int nattn = N_NODES / 8;   // 12500 full blocks

    // ---- fork: CSR build + layer-2 weight conversion on side stream ----
    cudaEventRecord(evFork, 0);
    cudaStreamWaitEvent(s2, evFork, 0);
    zero_counts_kernel<<<(N_NODES + 255) / 256, 256, 0, s2>>>();
    count_kernel<<<(N_EDGES + 255) / 256, 256, 0, s2>>>(ei);
    scan_kernel<<<1, 1024, 0, s2>>>();
    scatter_kernel<<<(N_EDGES + 255) / 256, 256, 0, s2>>>(ei);
    convert_w_kernel<1><<<(NCAT * FEAT + 255) / 256, 256, 0, s2>>>(Wq2, Wk2, Wv2, Ws2,
                                                                   bq2, bk2, bv2, bs2);
    cudaEventRecord(evJoin, s2);

    // ---- main stream: layer-1 weight conversion + GEMM (parallel with CSR) ----
    convert_w_kernel<0><<<(NCAT * FEAT + 255) / 256, 256>>>(Wq1, Wk1, Wv1, Ws1,
                                                            bq1, bk1, bv1, bs1);
    gemm_mma_kernel<0><<<M_TILES, 256, SMEM_BYTES>>>(x);

    // ---- join: attn1 needs CSR + gemm1 ----
    cudaStreamWaitEvent(0, evJoin, 0);
    attn1_kernel<<<nattn, 256>>>();

    // Layer 2 (weights already converted on side stream)
    gemm_mma_kernel<1><<<M_TILES, 256, SMEM_BYTES>>>(nullptr);
    attn2_kernel<<<nattn, 256>>>();

    // Classifier
    classifier_kernel<<<(N_NODES + 63) / 64, 256>>>(Wc, bc, out);
}

// round 16
// speedup vs baseline: 1.2866x; 1.0010x over previous
#include <cuda_runtime.h>
#include <cuda_fp16.h>
#include <cstdint>

#define N_NODES 100000
#define N_EDGES 1600000
#define FEAT 128
#define NCAT 512
#define M_TILES ((N_NODES + 127) / 128)
#define PAD_K 136   // fp16 elements per SMEM row (272B: 16B-aligned, conflict-free frags)

// ---------------- scratch (static __device__, no allocation) ----------------
__device__ __align__(16) float g_qsk[(size_t)N_NODES * 256];   // [node][q(128)|sk(128)] fp32, streamed
__device__ __align__(16) __half g_kvh[(size_t)N_NODES * 256];  // [node][32 x (k4|v4)] fp16, gather set (51MB)
__device__ __align__(16) float g_h1[N_NODES * FEAT];
__device__ __align__(16) float g_h2[N_NODES * FEAT];
__device__ __align__(16) __half g_wbh[2][NCAT * FEAT];  // per-layer B[n][k] = W[k][n], fp16 hi
__device__ __align__(16) __half g_wbl[2][NCAT * FEAT];  // fp16 lo (used by skip block only)
__device__ __align__(16) float g_bias[2][NCAT];
__device__ int g_counts[N_NODES];
__device__ int g_rowoff[N_NODES + 1];
__device__ int g_cursor[N_NODES];
__device__ int g_csrsrc[N_EDGES];

// ---------------- CSR build (edge_index is int32) ----------------
__global__ void zero_counts_kernel() {
    int i = blockIdx.x * blockDim.x + threadIdx.x;
    if (i < N_NODES) g_counts[i] = 0;
}
__global__ void count_kernel(const int* __restrict__ ei) {
    int e = blockIdx.x * blockDim.x + threadIdx.x;
    if (e < N_EDGES) atomicAdd(&g_counts[ei[N_EDGES + e]], 1);
}
__global__ void scan_kernel() {
    __shared__ int sums[1024];
    int tid = threadIdx.x;
    const int chunk = (N_NODES + 1023) / 1024;
    int begin = tid * chunk;
    int end = begin + chunk; if (end > N_NODES) end = N_NODES;
    int s = 0;
    for (int i = begin; i < end; i++) s += g_counts[i];
    sums[tid] = s;
    __syncthreads();
    for (int off = 1; off < 1024; off <<= 1) {
        int v = (tid >= off) ? sums[tid - off] : 0;
        __syncthreads();
        sums[tid] += v;
        __syncthreads();
    }
    int run = (tid == 0) ? 0 : sums[tid - 1];
    for (int i = begin; i < end; i++) {
        g_rowoff[i] = run;
        g_cursor[i] = run;
        run += g_counts[i];
    }
    if (tid == 1023) g_rowoff[N_NODES] = run;
}
__global__ void scatter_kernel(const int* __restrict__ ei) {
    int e = blockIdx.x * blockDim.x + threadIdx.x;
    if (e < N_EDGES) {
        int pos = atomicAdd(&g_cursor[ei[N_EDGES + e]], 1);
        g_csrsrc[pos] = ei[e];
    }
}

// ---------------- weight prep: B[n][k] = W[k][n], fp16 hi/lo + bias (per layer) ----------------
template <int LAYER>
__global__ void convert_w_kernel(const float* __restrict__ W0, const float* __restrict__ W1,
                                 const float* __restrict__ W2, const float* __restrict__ W3,
                                 const float* __restrict__ b0, const float* __restrict__ b1,
                                 const float* __restrict__ b2, const float* __restrict__ b3) {
    int i = blockIdx.x * blockDim.x + threadIdx.x;   // over 512*128
    if (i >= NCAT * FEAT) return;
    int n = i >> 7, k = i & 127;
    int widx = n >> 7, ncol = n & 127;
    const float* W = (widx == 0) ? W0 : (widx == 1) ? W1 : (widx == 2) ? W2 : W3;
    float w = W[k * 128 + ncol];
    __half h = __float2half_rn(w);
    g_wbh[LAYER][i] = h;
    g_wbl[LAYER][i] = __float2half_rn(w - __half2float(h));
    if (i < NCAT) {
        const float* B = (i < 128) ? b0 : (i < 256) ? b1 : (i < 384) ? b2 : b3;
        g_bias[LAYER][i] = B[i & 127];
    }
}

// ---------------- fp16 mma.sync GEMM with A-reuse over 4 output blocks ----------------
// Terms: q/k/v = 1 (Ah*Bh — outputs are fp16-bound anyway), skip = 3 (exact path).
__device__ __forceinline__ void mma16816(float c[4], uint32_t a0, uint32_t a1, uint32_t a2,
                                         uint32_t a3, uint32_t b0, uint32_t b1) {
    asm volatile(
        "mma.sync.aligned.m16n8k16.row.col.f32.f16.f16.f32 "
        "{%0,%1,%2,%3}, {%4,%5,%6,%7}, {%8,%9}, {%0,%1,%2,%3};"
        : "+f"(c[0]), "+f"(c[1]), "+f"(c[2]), "+f"(c[3])
        : "r"(a0), "r"(a1), "r"(a2), "r"(a3), "r"(b0), "r"(b1));
}
__device__ __forceinline__ uint32_t smem_u32(const void* p) {
    uint32_t a;
    asm("{ .reg .u64 t; cvta.to.shared.u64 t, %1; cvt.u32.u64 %0, t; }" : "=r"(a) : "l"(p));
    return a;
}
__device__ __forceinline__ void cp16(uint32_t s, const void* g) {
    asm volatile("cp.async.ca.shared.global [%0], [%1], 16;" :: "r"(s), "l"(g));
}
#define CP_COMMIT() asm volatile("cp.async.commit_group;" ::: "memory")
#define CP_WAIT(n)  asm volatile("cp.async.wait_group %0;" :: "n"(n) : "memory")

#define SM_TILE (128 * PAD_K)   // fp16 elements per tile
#define SMEM_BYTES (6 * SM_TILE * 2)   // [Ah | Al | Bh0 | Bl0 | Bh1 | Bl1]

// lo tile only needed for the skip block (nblk == 3)
template <int LAYER>
__device__ __forceinline__ void load_B(int nblk, int buf, uint32_t sb, int tid) {
    uint32_t bh = sb + (2 + 2 * buf) * SM_TILE * 2;
    uint32_t bl = bh + SM_TILE * 2;
    const __half* gh = g_wbh[LAYER] + nblk * 128 * FEAT;
    const __half* gl = g_wbl[LAYER] + nblk * 128 * FEAT;
    bool need_lo = (nblk == 3);
#pragma unroll
    for (int it = 0; it < 8; it++) {
        int p = tid + 256 * it;          // 0..2047
        int row = p >> 4, k8 = p & 15;
        uint32_t so = (uint32_t)(row * PAD_K + k8 * 8) * 2;
        cp16(bh + so, gh + p * 8);
        if (need_lo) cp16(bl + so, gl + p * 8);
    }
}

template <int SRC>
__global__ void __launch_bounds__(256, 1)
gemm_mma_kernel(const float* __restrict__ Xin) {
    extern __shared__ __half sm[];
    __half* sAh = sm;
    __half* sAl = sm + SM_TILE;
    uint32_t sb = smem_u32(sm);

    const float* X = (SRC == 0) ? Xin : (const float*)g_h1;
    int tid = threadIdx.x;
    int wid = tid >> 5, lane = tid & 31;
    int m0 = blockIdx.x * 128;

    load_B<SRC>(0, 0, sb, tid);
    CP_COMMIT();

    // A: load fp32 (streaming), split to fp16 hi/lo in registers, stage to smem
    const float4* X4 = (const float4*)X;
#pragma unroll
    for (int it = 0; it < 16; it++) {
        int q = tid + 256 * it;          // 0..4095
        int row = q >> 5, c4 = q & 31;
        int rg = m0 + row; if (rg > N_NODES - 1) rg = N_NODES - 1;
        float4 f = __ldcs(X4 + (size_t)rg * 32 + c4);
        __half h0 = __float2half_rn(f.x);
        __half h1 = __float2half_rn(f.y);
        __half h2 = __float2half_rn(f.z);
        __half h3 = __float2half_rn(f.w);
        __half l0 = __float2half_rn(f.x - __half2float(h0));
        __half l1 = __float2half_rn(f.y - __half2float(h1));
        __half l2 = __float2half_rn(f.z - __half2float(h2));
        __half l3 = __float2half_rn(f.w - __half2float(h3));
        __half2 hp0(h0, h1), hp1(h2, h3), lp0(l0, l1), lp1(l2, l3);
        uint2 hv, lv;
        hv.x = *(uint32_t*)&hp0; hv.y = *(uint32_t*)&hp1;
        lv.x = *(uint32_t*)&lp0; lv.y = *(uint32_t*)&lp1;
        int eo = row * PAD_K + c4 * 4;
        *(uint2*)&sAh[eo] = hv;
        *(uint2*)&sAl[eo] = lv;
    }

    load_B<SRC>(1, 1, sb, tid);
    CP_COMMIT();
    CP_WAIT(1);
    __syncthreads();

    int wm = wid >> 2, wn = wid & 3;
    int qid = lane >> 2, tq = (lane & 3) * 2;

    for (int nblk = 0; nblk < 4; nblk++) {
        __half* sBh = sm + (2 + 2 * (nblk & 1)) * SM_TILE;
        __half* sBl = sBh + SM_TILE;
        bool full = (nblk == 3);   // skip path: 3-term accuracy

        float c[4][4][4];
#pragma unroll
        for (int i = 0; i < 4; i++)
#pragma unroll
            for (int j = 0; j < 4; j++)
#pragma unroll
                for (int r = 0; r < 4; r++) c[i][j][r] = 0.f;

#pragma unroll
        for (int ks = 0; ks < 8; ks++) {
            int kb = ks * 16;
            uint32_t ah[4][4], al[4][4], bh[4][2], bl[4][2];
#pragma unroll
            for (int i = 0; i < 4; i++) {
                int r0 = (wm * 64 + i * 16 + qid) * PAD_K;
                int r8 = r0 + 8 * PAD_K;
                ah[i][0] = *(const uint32_t*)&sAh[r0 + kb + tq];
                ah[i][1] = *(const uint32_t*)&sAh[r8 + kb + tq];
                ah[i][2] = *(const uint32_t*)&sAh[r0 + kb + 8 + tq];
                ah[i][3] = *(const uint32_t*)&sAh[r8 + kb + 8 + tq];
                if (full) {
                    al[i][0] = *(const uint32_t*)&sAl[r0 + kb + tq];
                    al[i][1] = *(const uint32_t*)&sAl[r8 + kb + tq];
                    al[i][2] = *(const uint32_t*)&sAl[r0 + kb + 8 + tq];
                    al[i][3] = *(const uint32_t*)&sAl[r8 + kb + 8 + tq];
                }
            }
#pragma unroll
            for (int j = 0; j < 4; j++) {
                int n0 = (wn * 32 + j * 8 + qid) * PAD_K;
                bh[j][0] = *(const uint32_t*)&sBh[n0 + kb + tq];
                bh[j][1] = *(const uint32_t*)&sBh[n0 + kb + 8 + tq];
                if (full) {
                    bl[j][0] = *(const uint32_t*)&sBl[n0 + kb + tq];
                    bl[j][1] = *(const uint32_t*)&sBl[n0 + kb + 8 + tq];
                }
            }
#pragma unroll
            for (int i = 0; i < 4; i++)
#pragma unroll
                for (int j = 0; j < 4; j++) {
                    mma16816(c[i][j], ah[i][0], ah[i][1], ah[i][2], ah[i][3], bh[j][0], bh[j][1]);
                    if (full) {
                        mma16816(c[i][j], al[i][0], al[i][1], al[i][2], al[i][3], bh[j][0], bh[j][1]);
                        mma16816(c[i][j], ah[i][0], ah[i][1], ah[i][2], ah[i][3], bl[j][0], bl[j][1]);
                    }
                }
        }

        // epilogue routing:
        //   q (0), sk (3) -> fp32 g_qsk (streaming store) at col offset 0 / 128
        //   k (1), v (2)  -> fp16 g_kvh interleaved (default store: keep L2-resident)
        bool is_qsk = (nblk == 0 || nblk == 3);
        int colofs = (nblk == 3) ? 128 : 0;
        int sel = (nblk == 2) ? 1 : 0;
#pragma unroll
        for (int i = 0; i < 4; i++) {
            int row = m0 + wm * 64 + i * 16 + qid;
#pragma unroll
            for (int j = 0; j < 4; j++) {
                int col = wn * 32 + j * 8 + tq;   // even, pair (col, col+1) in same 4-chunk
                float2 bb = *(const float2*)&g_bias[SRC][nblk * 128 + col];
                float2 o0 = {c[i][j][0] + bb.x, c[i][j][1] + bb.y};
                float2 o1 = {c[i][j][2] + bb.x, c[i][j][3] + bb.y};
                if (is_qsk) {
                    if (row < N_NODES)
                        __stcs((float2*)&g_qsk[(size_t)row * 256 + colofs + col], o0);
                    if (row + 8 < N_NODES)
                        __stcs((float2*)&g_qsk[(size_t)(row + 8) * 256 + colofs + col], o1);
                } else {
                    uint32_t eo = (uint32_t)((col >> 2) * 8 + sel * 4 + (col & 3));
                    if (row < N_NODES) {
                        __half2 p = __floats2half2_rn(o0.x, o0.y);
                        *(__half2*)&g_kvh[(size_t)row * 256 + eo] = p;
                    }
                    if (row + 8 < N_NODES) {
                        __half2 p = __floats2half2_rn(o1.x, o1.y);
                        *(__half2*)&g_kvh[(size_t)(row + 8) * 256 + eo] = p;
                    }
                }
            }
        }

        if (nblk < 3) {
            __syncthreads();
            if (nblk + 2 <= 3) {
                load_B<SRC>(nblk + 2, nblk & 1, sb, tid);
                CP_COMMIT();
                CP_WAIT(1);
            } else {
                CP_WAIT(0);
            }
            __syncthreads();
        }
    }
}

// ---------------- attention core: one LDG.128/edge (fp16 k4|v4), 2-edge pipeline ----------------
// q/sk: __ldcs (read-once streaming) so the 51MB kv gather set keeps L2 residency.
__device__ __forceinline__ float4 attn_node(int node, int lane) {
    const float4* qsk = (const float4*)g_qsk;        // 64 float4 per row
    const uint4*  kvh = (const uint4*)g_kvh;         // 32 uint4 per row: [k4(fp16)|v4(fp16)]

    float4 qv = __ldcs(qsk + (size_t)node * 64 + lane);
    qv.x *= 0.125f; qv.y *= 0.125f; qv.z *= 0.125f; qv.w *= 0.125f;  // 1/sqrt(64)

    int e0 = g_rowoff[node];
    int e1 = g_rowoff[node + 1];

    float sA = 0.f, sB = 0.f;
    float4 aA = {0.f, 0.f, 0.f, 0.f}, aB = {0.f, 0.f, 0.f, 0.f};

    int e = e0;
    for (; e + 2 <= e1; e += 2) {
        int s0 = g_csrsrc[e];
        int s1 = g_csrsrc[e + 1];
        uint4 c0 = kvh[(size_t)s0 * 32 + lane];
        uint4 c1 = kvh[(size_t)s1 * 32 + lane];
        float2 k0a = __half22float2(*(__half2*)&c0.x);
        float2 k0b = __half22float2(*(__half2*)&c0.y);
        float2 v0a = __half22float2(*(__half2*)&c0.z);
        float2 v0b = __half22float2(*(__half2*)&c0.w);
        float2 k1a = __half22float2(*(__half2*)&c1.x);
        float2 k1b = __half22float2(*(__half2*)&c1.y);
        float2 v1a = __half22float2(*(__half2*)&c1.z);
        float2 v1b = __half22float2(*(__half2*)&c1.w);
        float d0 = fmaf(qv.x, k0a.x, fmaf(qv.y, k0a.y, fmaf(qv.z, k0b.x, qv.w * k0b.y)));
        float d1 = fmaf(qv.x, k1a.x, fmaf(qv.y, k1a.y, fmaf(qv.z, k1b.x, qv.w * k1b.y)));
        d0 += __shfl_xor_sync(0xffffffffu, d0, 8);
        d1 += __shfl_xor_sync(0xffffffffu, d1, 8);
        d0 += __shfl_xor_sync(0xffffffffu, d0, 4);
        d1 += __shfl_xor_sync(0xffffffffu, d1, 4);
        d0 += __shfl_xor_sync(0xffffffffu, d0, 2);
        d1 += __shfl_xor_sync(0xffffffffu, d1, 2);
        d0 += __shfl_xor_sync(0xffffffffu, d0, 1);
        d1 += __shfl_xor_sync(0xffffffffu, d1, 1);
        float w0 = __expf(d0);
        float w1 = __expf(d1);
        sA += w0; sB += w1;
        aA.x = fmaf(w0, v0a.x, aA.x); aB.x = fmaf(w1, v1a.x, aB.x);
        aA.y = fmaf(w0, v0a.y, aA.y); aB.y = fmaf(w1, v1a.y, aB.y);
        aA.z = fmaf(w0, v0b.x, aA.z); aB.z = fmaf(w1, v1b.x, aB.z);
        aA.w = fmaf(w0, v0b.y, aA.w); aB.w = fmaf(w1, v1b.y, aB.w);
    }
    if (e < e1) {
        int s0 = g_csrsrc[e];
        uint4 c0 = kvh[(size_t)s0 * 32 + lane];
        float2 k0a = __half22float2(*(__half2*)&c0.x);
        float2 k0b = __half22float2(*(__half2*)&c0.y);
        float2 v0a = __half22float2(*(__half2*)&c0.z);
        float2 v0b = __half22float2(*(__half2*)&c0.w);
        float d0 = fmaf(qv.x, k0a.x, fmaf(qv.y, k0a.y, fmaf(qv.z, k0b.x, qv.w * k0b.y)));
        d0 += __shfl_xor_sync(0xffffffffu, d0, 8);
        d0 += __shfl_xor_sync(0xffffffffu, d0, 4);
        d0 += __shfl_xor_sync(0xffffffffu, d0, 2);
        d0 += __shfl_xor_sync(0xffffffffu, d0, 1);
        float w0 = __expf(d0);
        sA += w0;
        aA.x = fmaf(w0, v0a.x, aA.x);
        aA.y = fmaf(w0, v0a.y, aA.y);
        aA.z = fmaf(w0, v0b.x, aA.z);
        aA.w = fmaf(w0, v0b.y, aA.w);
    }

    float s = sA + sB;
    float inv = 1.0f / fmaxf(s, 1e-16f);
    float4 sk = __ldcs(qsk + (size_t)node * 64 + 32 + lane);
    float4 o;
    o.x = fmaf(aA.x + aB.x, inv, sk.x);
    o.y = fmaf(aA.y + aB.y, inv, sk.y);
    o.z = fmaf(aA.z + aB.z, inv, sk.z);
    o.w = fmaf(aA.w + aB.w, inv, sk.w);
    return o;
}

// Layer 1: attn + ELU -> g_h1 (fp32, streaming store; layer-2 GEMM converts inline)
__global__ void attn1_kernel() {
    int node = blockIdx.x * 8 + (threadIdx.x >> 5);   // N_NODES % 8 == 0
    int lane = threadIdx.x & 31;
    float4 o = attn_node(node, lane);
    o.x = (o.x > 0.f) ? o.x : expm1f(o.x);
    o.y = (o.y > 0.f) ? o.y : expm1f(o.y);
    o.z = (o.z > 0.f) ? o.z : expm1f(o.z);
    o.w = (o.w > 0.f) ? o.w : expm1f(o.w);
    __stcs((float4*)g_h1 + (size_t)node * 32 + lane, o);
}

// Layer 2: attn -> g_h2 (streaming store)
__global__ void attn2_kernel() {
    int node = blockIdx.x * 8 + (threadIdx.x >> 5);
    int lane = threadIdx.x & 31;
    float4 o = attn_node(node, lane);
    __stcs((float4*)g_h2 + (size_t)node * 32 + lane, o);
}

// ---------------- classifier: out = g_h2 @ Wc + bc  (128 -> 40) ----------------
__global__ void classifier_kernel(const float* __restrict__ Wc,
                                  const float* __restrict__ bc,
                                  float* __restrict__ out) {
    const float* H = (const float*)g_h2;
    __shared__ float Ws[128 * 40];
    for (int i = threadIdx.x; i < 128 * 40; i += 256) Ws[i] = Wc[i];
    __syncthreads();

    int cg = threadIdx.x & 7;
    int nr = threadIdx.x >> 3;
    int n0 = blockIdx.x * 64 + nr * 2;

    int r0 = (n0     < N_NODES) ? n0     : N_NODES - 1;
    int r1 = (n0 + 1 < N_NODES) ? n0 + 1 : N_NODES - 1;
    const float* h0p = H + (size_t)r0 * 128;
    const float* h1p = H + (size_t)r1 * 128;

    float a0[5] = {0, 0, 0, 0, 0};
    float a1[5] = {0, 0, 0, 0, 0};
#pragma unroll 4
    for (int k = 0; k < 128; k++) {
        float h0 = __ldcs(h0p + k);
        float h1 = __ldcs(h1p + k);
#pragma unroll
        for (int j = 0; j < 5; j++) {
            float w = Ws[k * 40 + cg * 5 + j];
            a0[j] = fmaf(h0, w, a0[j]);
            a1[j] = fmaf(h1, w, a1[j]);
        }
    }
    if (n0 < N_NODES)
#pragma unroll
        for (int j = 0; j < 5; j++) out[(size_t)n0 * 40 + cg * 5 + j] = a0[j] + bc[cg * 5 + j];
    if (n0 + 1 < N_NODES)
#pragma unroll
        for (int j = 0; j < 5; j++) out[(size_t)(n0 + 1) * 40 + cg * 5 + j] = a1[j] + bc[cg * 5 + j];
}

// ---------------- launch ----------------
extern "C" void kernel_launch(void* const* d_in, const int* in_sizes, int n_in,
                              void* d_out, int out_size) {
    const float* x   = (const float*)d_in[0];
    const int*   ei  = (const int*)d_in[1];   // int32 (JAX x64-disabled)
    const float* Wq1 = (const float*)d_in[2];  const float* bq1 = (const float*)d_in[3];
    const float* Wk1 = (const float*)d_in[4];  const float* bk1 = (const float*)d_in[5];
    const float* Wv1 = (const float*)d_in[6];  const float* bv1 = (const float*)d_in[7];
    const float* Ws1 = (const float*)d_in[8];  const float* bs1 = (const float*)d_in[9];
    const float* Wq2 = (const float*)d_in[10]; const float* bq2 = (const float*)d_in[11];
    const float* Wk2 = (const float*)d_in[12]; const float* bk2 = (const float*)d_in[13];
    const float* Wv2 = (const float*)d_in[14]; const float* bv2 = (const float*)d_in[15];
    const float* Ws2 = (const float*)d_in[16]; const float* bs2 = (const float*)d_in[17];
    const float* Wc  = (const float*)d_in[18]; const float* bc  = (const float*)d_in[19];
    float* out = (float*)d_out;

    static int configured = 0;
    static cudaStream_t s2;
    static cudaEvent_t evFork, evJoin;
    if (!configured) {
        cudaFuncSetAttribute(gemm_mma_kernel<0>, cudaFuncAttributeMaxDynamicSharedMemorySize,
                             SMEM_BYTES);
        cudaFuncSetAttribute(gemm_mma_kernel<1>, cudaFuncAttributeMaxDynamicSharedMemorySize,
                             SMEM_BYTES);
        cudaStreamCreateWithFlags(&s2, cudaStreamNonBlocking);
        cudaEventCreateWithFlags(&evFork, cudaEventDisableTiming);
        cudaEventCreateWithFlags(&evJoin, cudaEventDisableTiming);
        configured = 1;
    }

    int nattn = N_NODES / 8;   // 12500 full blocks

    // ---- fork: CSR build + layer-2 weight conversion on side stream ----
    cudaEventRecord(evFork, 0);
    cudaStreamWaitEvent(s2, evFork, 0);
    zero_counts_kernel<<<(N_NODES + 255) / 256, 256, 0, s2>>>();
    count_kernel<<<(N_EDGES + 255) / 256, 256, 0, s2>>>(ei);
    scan_kernel<<<1, 1024, 0, s2>>>();
    scatter_kernel<<<(N_EDGES + 255) / 256, 256, 0, s2>>>(ei);
    convert_w_kernel<1><<<(NCAT * FEAT + 255) / 256, 256, 0, s2>>>(Wq2, Wk2, Wv2, Ws2,
                                                                   bq2, bk2, bv2, bs2);
    cudaEventRecord(evJoin, s2);

    // ---- main stream: layer-1 weight conversion + GEMM (parallel with CSR) ----
    convert_w_kernel<0><<<(NCAT * FEAT + 255) / 256, 256>>>(Wq1, Wk1, Wv1, Ws1,
                                                            bq1, bk1, bv1, bs1);
    gemm_mma_kernel<0><<<M_TILES, 256, SMEM_BYTES>>>(x);

    // ---- join: attn1 needs CSR + gemm1 ----
    cudaStreamWaitEvent(0, evJoin, 0);
    attn1_kernel<<<nattn, 256>>>();

    // Layer 2 (weights already converted on side stream)
    gemm_mma_kernel<1><<<M_TILES, 256, SMEM_BYTES>>>(nullptr);
    attn2_kernel<<<nattn, 256>>>();

    // Classifier
    classifier_kernel<<<(N_NODES + 63) / 64, 256>>>(Wc, bc, out);
}